// round 7
// baseline (speedup 1.0000x reference)
#include <cuda_runtime.h>
#include <cuda_fp16.h>
#include <math.h>
#include <stdint.h>

#define BB 2
#define SS 2048
#define HH 16
#define DD 128
#define HID (HH*DD)
#define SM_SCALE_L2E 0.12751649736230442f   /* (1/sqrt(128)) * log2(e) */

// ---------------- scratch (no allocation allowed) ----------------
__device__ signed char g_k8[(size_t)BB*HH*SS*DD];
__device__ __half      g_v16[(size_t)BB*HH*SS*DD];
__device__ float g_kscale[BB*HH*(SS/64)];
__device__ float g_vmean[BB*HH*DD];
__device__ float g_kpart[BB*HH*32*DD];
__device__ float g_vpart[BB*HH*32*DD];

// ---------------- K0: k/v mean partials ----------------
__global__ void __launch_bounds__(256)
pre_k0(const float* __restrict__ k, const float* __restrict__ v){
  int bh = blockIdx.y, bx = blockIdx.x;
  int b = bh >> 4, h = bh & 15;
  int t = threadIdx.x;
  int d = t & 127, hf = t >> 7;
  size_t base = ((size_t)b*SS + (size_t)bx*128 + (size_t)hf*64)*HID + h*DD + d;
  float ka = 0.f, va = 0.f;
  #pragma unroll 4
  for (int r2 = 0; r2 < 64; r2++){
    ka += k[base + (size_t)r2*HID];
    va += v[base + (size_t)r2*HID];
  }
  g_kpart[((bh*16 + bx)*2 + hf)*DD + d] = ka;
  g_vpart[((bh*16 + bx)*2 + hf)*DD + d] = va;
}

// ---------------- K1: quant_k (bx<32) + smooth_v (bx>=32) ----------------
__global__ void __launch_bounds__(256)
pre_k2(const float* __restrict__ k, const float* __restrict__ v){
  __shared__ float smean[128];
  int bh = blockIdx.y, bx = blockIdx.x;
  int b = bh >> 4, h = bh & 15;
  int t = threadIdx.x;
  if (t < 128){
    const float* part = (bx < 32) ? g_kpart : g_vpart;
    float a = 0.f;
    #pragma unroll
    for (int c = 0; c < 32; c++) a += part[(bh*32 + c)*DD + t];
    smean[t] = a / (float)SS;
    if (bx >= 32) g_vmean[bh*DD + t] = smean[t];
  }
  __syncthreads();
  if (bx < 32){
    __shared__ float red[8];
    int g = bx;
    size_t inbase = ((size_t)b*SS + (size_t)g*64)*HID + h*DD;
    float4 vals[8]; float amax = 0.f;
    #pragma unroll
    for (int i = 0; i < 8; i++){
      int f4 = t + i*256;
      int row = f4 >> 5, c4 = f4 & 31;
      float4 x = *(const float4*)(k + inbase + (size_t)row*HID + c4*4);
      x.x -= smean[c4*4]; x.y -= smean[c4*4+1]; x.z -= smean[c4*4+2]; x.w -= smean[c4*4+3];
      vals[i] = x;
      amax = fmaxf(amax, fmaxf(fmaxf(fabsf(x.x), fabsf(x.y)), fmaxf(fabsf(x.z), fabsf(x.w))));
    }
    #pragma unroll
    for (int o = 16; o > 0; o >>= 1)
      amax = fmaxf(amax, __shfl_xor_sync(0xffffffffu, amax, o));
    if ((t & 31) == 0) red[t >> 5] = amax;
    __syncthreads();
    float r0 = red[0];
    #pragma unroll
    for (int i = 1; i < 8; i++) r0 = fmaxf(r0, red[i]);
    float scale = fmaxf(r0 / 127.0f, 1e-8f);
    size_t obase = ((size_t)bh*SS + (size_t)g*64)*DD;
    #pragma unroll
    for (int i = 0; i < 8; i++){
      int f4 = t + i*256;
      int row = f4 >> 5, c4 = f4 & 31;
      char4 o;
      o.x = (signed char)(int)fminf(fmaxf(rintf(vals[i].x / scale), -127.f), 127.f);
      o.y = (signed char)(int)fminf(fmaxf(rintf(vals[i].y / scale), -127.f), 127.f);
      o.z = (signed char)(int)fminf(fmaxf(rintf(vals[i].z / scale), -127.f), 127.f);
      o.w = (signed char)(int)fminf(fmaxf(rintf(vals[i].w / scale), -127.f), 127.f);
      *(char4*)(g_k8 + obase + (size_t)row*DD + c4*4) = o;
    }
    if (t == 0) g_kscale[bh*32 + g] = scale;
  } else {
    int g = bx - 32;
    size_t inbase = ((size_t)b*SS + (size_t)g*64)*HID + h*DD;
    size_t obase  = ((size_t)bh*SS + (size_t)g*64)*DD;
    #pragma unroll
    for (int i = 0; i < 8; i++){
      int f4 = t + i*256;
      int row = f4 >> 5, c4 = f4 & 31;
      float4 x = *(const float4*)(v + inbase + (size_t)row*HID + c4*4);
      __half2 h0 = __floats2half2_rn(x.x - smean[c4*4],   x.y - smean[c4*4+1]);
      __half2 h1 = __floats2half2_rn(x.z - smean[c4*4+2], x.w - smean[c4*4+3]);
      uint2 o; o.x = *(uint32_t*)&h0; o.y = *(uint32_t*)&h1;
      *(uint2*)(g_v16 + obase + (size_t)row*DD + c4*4) = o;
    }
  }
}

// ---------------- MMA helpers ----------------
__device__ __forceinline__ void mma16816(float c[4], const uint32_t a[4], uint32_t b0, uint32_t b1){
  asm volatile(
    "mma.sync.aligned.m16n8k16.row.col.f32.f16.f16.f32 "
    "{%0,%1,%2,%3}, {%4,%5,%6,%7}, {%8,%9}, {%0,%1,%2,%3};\n"
    : "+f"(c[0]), "+f"(c[1]), "+f"(c[2]), "+f"(c[3])
    : "r"(a[0]), "r"(a[1]), "r"(a[2]), "r"(a[3]), "r"(b0), "r"(b1));
}
__device__ __forceinline__ void mma_s8(int c[4], const uint32_t a[4], uint32_t b0, uint32_t b1){
  asm volatile(
    "mma.sync.aligned.m16n8k32.row.col.s32.s8.s8.s32 "
    "{%0,%1,%2,%3}, {%4,%5,%6,%7}, {%8,%9}, {%0,%1,%2,%3};\n"
    : "+r"(c[0]), "+r"(c[1]), "+r"(c[2]), "+r"(c[3])
    : "r"(a[0]), "r"(a[1]), "r"(a[2]), "r"(a[3]), "r"(b0), "r"(b1));
}
__device__ __forceinline__ void ldmx4(uint32_t& t0, uint32_t& t1, uint32_t& t2, uint32_t& t3, uint32_t addr){
  asm volatile("ldmatrix.sync.aligned.m8n8.x4.shared.b16 {%0,%1,%2,%3}, [%4];\n"
    : "=r"(t0), "=r"(t1), "=r"(t2), "=r"(t3) : "r"(addr));
}
__device__ __forceinline__ void ldmx4t(uint32_t& t0, uint32_t& t1, uint32_t& t2, uint32_t& t3, uint32_t addr){
  asm volatile("ldmatrix.sync.aligned.m8n8.x4.trans.shared.b16 {%0,%1,%2,%3}, [%4];\n"
    : "=r"(t0), "=r"(t1), "=r"(t2), "=r"(t3) : "r"(addr));
}
#define CP16(dst, src) asm volatile("cp.async.cg.shared.global [%0], [%1], 16;\n" :: "r"(dst), "l"(src) : "memory")
#define CP_COMMIT() asm volatile("cp.async.commit_group;\n" ::: "memory")
#define CP_WAIT0()  asm volatile("cp.async.wait_group 0;\n" ::: "memory")
#define CP_WAIT1()  asm volatile("cp.async.wait_group 1;\n" ::: "memory")

#define KPITCH 144
#define VPITCH 272
#define STAGE_SZ (64*KPITCH + 64*VPITCH)       /* 26624 */
#define SK_OFF(st) ((st)*STAGE_SZ)
#define SV_OFF(st) ((st)*STAGE_SZ + 64*KPITCH)
#define QSTAGE_OFF (2*STAGE_SZ)                /* f32 Q staging in stages 2+3 region */
#define QPITCHF 132
#define SMEM_TOTAL (4*STAGE_SZ)                /* 106496 */

// ---------------- main attention kernel ----------------
__global__ void __launch_bounds__(128, 2)
attn_kernel(const float* __restrict__ qsrc,
            const int* __restrict__ wlp, const int* __restrict__ wrp,
            float* __restrict__ out){
  extern __shared__ char smem[];
  __shared__ float qred[4];
  const uint32_t smem_b = (uint32_t)__cvta_generic_to_shared(smem);

  const int bx = blockIdx.x;
  const int xq = (bx & 1) ? (16 + (bx >> 1)) : (15 - (bx >> 1));
  const int i0  = xq * 64;
  const int bh  = blockIdx.y;
  const int b   = bh >> 4, h = bh & 15;
  const int tid = threadIdx.x, wid = tid >> 5, lane = tid & 31;
  const int r   = lane >> 2, q2 = (lane & 3) * 2, c4 = (lane & 3) * 4;
  const int wl = *wlp, wr = *wrp;

  const signed char* Kg = g_k8 + (size_t)bh*SS*DD;
  const __half*      Vg = g_v16 + (size_t)bh*SS*DD;
  const int qrow = wid*16 + r;

  int jlo = (wl >= 0) ? max(0, i0 - wl) : 0;
  int jhi = (wr >= 0) ? min(SS-1, i0 + 63 + wr) : SS-1;
  const int jloT = jlo & ~63;
  const int nt = ((jhi - jloT) >> 6) + 1;

  auto issue = [&](int st, int j0){
    uint32_t kb = smem_b + SK_OFF(st);
    const signed char* kg = Kg + (size_t)j0*128;
    #pragma unroll
    for (int c = tid; c < 512; c += 128){
      int row = c >> 3, seg = c & 7;
      CP16(kb + row*KPITCH + seg*16, kg + row*128 + seg*16);
    }
    uint32_t vb = smem_b + SV_OFF(st);
    const __half* vg = Vg + (size_t)j0*128;
    #pragma unroll
    for (int c = tid; c < 1024; c += 128){
      int row = c >> 4, seg = c & 15;
      CP16(vb + row*VPITCH + seg*16, (const char*)vg + row*256 + seg*16);
    }
    CP_COMMIT();
  };

  // prefetch tiles 0,1 into stages 0,1 (Q staging lives in stages 2+3)
  issue(0, jloT);
  if (nt > 1) issue(1, jloT + 64);

  // ---- prologue: stage Q (f32), quantize in-kernel ----
  {
    const float* qf = qsrc + ((size_t)b*SS + i0)*HID + h*DD;
    float* sQf = (float*)(smem + QSTAGE_OFF);
    #pragma unroll
    for (int itq = tid; itq < 2048; itq += 128){
      int row = itq >> 5, g4 = itq & 31;
      *(float4*)(sQf + row*QPITCHF + g4*4) = *(const float4*)(qf + (size_t)row*HID + g4*4);
    }
  }
  __syncthreads();
  float qscale;
  uint32_t afrag[4][4];
  {
    const float* sQf = (const float*)(smem + QSTAGE_OFF);
    float amax = 0.f;
    #pragma unroll
    for (int kc = 0; kc < 4; kc++){
      #pragma unroll
      for (int j = 0; j < 4; j++){
        int row = (j & 1) ? qrow + 8 : qrow;
        int col = kc*32 + c4 + ((j & 2) ? 16 : 0);
        float4 x = *(const float4*)(sQf + row*QPITCHF + col);
        amax = fmaxf(amax, fmaxf(fmaxf(fabsf(x.x), fabsf(x.y)), fmaxf(fabsf(x.z), fabsf(x.w))));
      }
    }
    #pragma unroll
    for (int o = 16; o > 0; o >>= 1)
      amax = fmaxf(amax, __shfl_xor_sync(0xffffffffu, amax, o));
    if (lane == 0) qred[wid] = amax;
    __syncthreads();
    qscale = fmaxf(fmaxf(qred[wid], qred[wid ^ 1]) / 127.0f, 1e-8f);
    #pragma unroll
    for (int kc = 0; kc < 4; kc++){
      #pragma unroll
      for (int j = 0; j < 4; j++){
        int row = (j & 1) ? qrow + 8 : qrow;
        int col = kc*32 + c4 + ((j & 2) ? 16 : 0);
        float4 x = *(const float4*)(sQf + row*QPITCHF + col);
        int b0 = (int)fminf(fmaxf(rintf(x.x / qscale), -127.f), 127.f);
        int b1 = (int)fminf(fmaxf(rintf(x.y / qscale), -127.f), 127.f);
        int b2 = (int)fminf(fmaxf(rintf(x.z / qscale), -127.f), 127.f);
        int b3 = (int)fminf(fmaxf(rintf(x.w / qscale), -127.f), 127.f);
        afrag[kc][j] = (uint32_t)(b0 & 0xff) | ((uint32_t)(b1 & 0xff) << 8)
                     | ((uint32_t)(b2 & 0xff) << 16) | ((uint32_t)(b3 & 0xff) << 24);
      }
    }
  }
  __syncthreads();   // Q staging (stages 2/3) free for cp.async reuse

  const float qsl = qscale * SM_SCALE_L2E;
  const int i_r0 = i0 + qrow, i_r1 = i_r0 + 8;
  const int lo0 = (wl < 0) ? -0x40000000 : i_r0 - wl;
  const int hi0 = (wr < 0) ?  0x40000000 : i_r0 + wr;
  const int lo1 = (wl < 0) ? -0x40000000 : i_r1 - wl;
  const int hi1 = (wr < 0) ?  0x40000000 : i_r1 + wr;

  float of[16][4];
  #pragma unroll
  for (int n = 0; n < 16; n++){ of[n][0]=0.f; of[n][1]=0.f; of[n][2]=0.f; of[n][3]=0.f; }
  float m0 = -1e30f, m1 = -1e30f, l0 = 0.f, l1 = 0.f;

  const int ldm_g = lane >> 3;
  const uint32_t kfrag_off = (uint32_t)(((ldm_g >> 1)*8 + (lane & 7))*KPITCH + (ldm_g & 1)*16);
  const int jrow = lane & 15;
  const int dsel = (lane & 16) ? 8 : 0;

  int accbuf[2][8][4];

  // ============ pipelined mainloop: QK(t) || softmax+PV(t-1) ============
  for (int t = 0; t <= nt; t++){
    if (t < nt){
      if (t + 2 <= nt) { CP_WAIT1(); } else { CP_WAIT0(); }
      __syncthreads();
      if (t + 2 < nt) issue((t + 2) & 3, jloT + (t + 2)*64);

      int (*acc)[4] = accbuf[t & 1];
      #pragma unroll
      for (int n = 0; n < 8; n++){ acc[n][0]=0; acc[n][1]=0; acc[n][2]=0; acc[n][3]=0; }
      const uint32_t kfb = smem_b + SK_OFF(t & 3) + kfrag_off;
      #pragma unroll
      for (int mm = 0; mm < 16; mm++){
        const int kc = mm >> 2, nfp = mm & 3;
        uint32_t b0, b1, b2, b3;
        ldmx4(b0, b1, b2, b3, kfb + nfp*(16*KPITCH) + kc*32);
        mma_s8(acc[nfp*2    ], afrag[kc], b0, b1);
        mma_s8(acc[nfp*2 + 1], afrag[kc], b2, b3);
      }
    }

    if (t >= 1){
      const int tp = t - 1;
      const int j0 = jloT + tp*64;
      int (*acc)[4] = accbuf[tp & 1];
      const float dq = qsl * g_kscale[bh*(SS/64) + (j0 >> 6)];
      float sf[8][4];
      float mt0 = -INFINITY, mt1 = -INFINITY;
      const bool full = ((wl < 0) || (j0 >= i0 + 63 - wl)) && ((wr < 0) || (j0 + 63 <= i0 + wr));
      if (full){
        #pragma unroll
        for (int nf = 0; nf < 8; nf++){
          float s00 = __int2float_rn(acc[nf][0]) * dq;
          float s01 = __int2float_rn(acc[nf][1]) * dq;
          float s10 = __int2float_rn(acc[nf][2]) * dq;
          float s11 = __int2float_rn(acc[nf][3]) * dq;
          sf[nf][0]=s00; sf[nf][1]=s01; sf[nf][2]=s10; sf[nf][3]=s11;
          mt0 = fmaxf(mt0, fmaxf(s00, s01));
          mt1 = fmaxf(mt1, fmaxf(s10, s11));
        }
      } else {
        #pragma unroll
        for (int nf = 0; nf < 8; nf++){
          int jc = j0 + nf*8 + q2;
          float s00 = (jc   >= lo0 && jc   <= hi0) ? __int2float_rn(acc[nf][0]) * dq : -INFINITY;
          float s01 = (jc+1 >= lo0 && jc+1 <= hi0) ? __int2float_rn(acc[nf][1]) * dq : -INFINITY;
          float s10 = (jc   >= lo1 && jc   <= hi1) ? __int2float_rn(acc[nf][2]) * dq : -INFINITY;
          float s11 = (jc+1 >= lo1 && jc+1 <= hi1) ? __int2float_rn(acc[nf][3]) * dq : -INFINITY;
          sf[nf][0]=s00; sf[nf][1]=s01; sf[nf][2]=s10; sf[nf][3]=s11;
          mt0 = fmaxf(mt0, fmaxf(s00, s01));
          mt1 = fmaxf(mt1, fmaxf(s10, s11));
        }
      }
      mt0 = fmaxf(mt0, __shfl_xor_sync(0xffffffffu, mt0, 1));
      mt0 = fmaxf(mt0, __shfl_xor_sync(0xffffffffu, mt0, 2));
      mt1 = fmaxf(mt1, __shfl_xor_sync(0xffffffffu, mt1, 1));
      mt1 = fmaxf(mt1, __shfl_xor_sync(0xffffffffu, mt1, 2));

      const bool raise = (mt0 > m0) || (mt1 > m1);
      float mn0 = fmaxf(m0, mt0), mn1 = fmaxf(m1, mt1);
      float a0 = exp2f(m0 - mn0), a1 = exp2f(m1 - mn1);
      float t0 = 0.f, t1 = 0.f;
      #pragma unroll
      for (int nf = 0; nf < 8; nf++){
        float e00 = exp2f(sf[nf][0] - mn0);
        float e01 = exp2f(sf[nf][1] - mn0);
        float e10 = exp2f(sf[nf][2] - mn1);
        float e11 = exp2f(sf[nf][3] - mn1);
        sf[nf][0]=e00; sf[nf][1]=e01; sf[nf][2]=e10; sf[nf][3]=e11;
        t0 += e00 + e01; t1 += e10 + e11;
      }
      l0 = l0*a0 + t0; l1 = l1*a1 + t1;
      m0 = mn0; m1 = mn1;
      if (__ballot_sync(0xffffffffu, raise)){
        #pragma unroll
        for (int n = 0; n < 16; n++){
          of[n][0]*=a0; of[n][1]*=a0; of[n][2]*=a1; of[n][3]*=a1;
        }
      }

      uint32_t pfrag[4][4];
      #pragma unroll
      for (int kc = 0; kc < 4; kc++){
        __half2 p0 = __floats2half2_rn(sf[2*kc  ][0], sf[2*kc  ][1]);
        __half2 p1 = __floats2half2_rn(sf[2*kc  ][2], sf[2*kc  ][3]);
        __half2 p2 = __floats2half2_rn(sf[2*kc+1][0], sf[2*kc+1][1]);
        __half2 p3 = __floats2half2_rn(sf[2*kc+1][2], sf[2*kc+1][3]);
        pfrag[kc][0] = *(uint32_t*)&p0; pfrag[kc][1] = *(uint32_t*)&p1;
        pfrag[kc][2] = *(uint32_t*)&p2; pfrag[kc][3] = *(uint32_t*)&p3;
      }

      const uint32_t svb = smem_b + SV_OFF(tp & 3);
      #pragma unroll
      for (int jc = 0; jc < 4; jc++){
        #pragma unroll
        for (int dc = 0; dc < 8; dc++){
          uint32_t addr = svb + (jc*16 + jrow)*VPITCH + (dc*16 + dsel)*2;
          uint32_t v0, v1, v2, v3;
          ldmx4t(v0, v1, v2, v3, addr);
          mma16816(of[dc*2    ], pfrag[jc], v0, v1);
          mma16816(of[dc*2 + 1], pfrag[jc], v2, v3);
        }
      }
    }
  }

  // --- epilogue: reduce l over quad, normalize, f16-round, add v_mean ---
  l0 += __shfl_xor_sync(0xffffffffu, l0, 1);
  l0 += __shfl_xor_sync(0xffffffffu, l0, 2);
  l1 += __shfl_xor_sync(0xffffffffu, l1, 1);
  l1 += __shfl_xor_sync(0xffffffffu, l1, 2);
  float inv0 = 1.0f / l0, inv1 = 1.0f / l1;
  float* ob = out + ((size_t)b*SS)*HID + h*DD;
  const float* vm = g_vmean + bh*DD;
  #pragma unroll
  for (int n = 0; n < 16; n++){
    int d0 = n*8 + q2;
    float2 o0, o1;
    o0.x = __half2float(__float2half_rn(of[n][0]*inv0)) + vm[d0];
    o0.y = __half2float(__float2half_rn(of[n][1]*inv0)) + vm[d0+1];
    o1.x = __half2float(__float2half_rn(of[n][2]*inv1)) + vm[d0];
    o1.y = __half2float(__float2half_rn(of[n][3]*inv1)) + vm[d0+1];
    *(float2*)(ob + (size_t)i_r0*HID + d0) = o0;
    *(float2*)(ob + (size_t)i_r1*HID + d0) = o1;
  }
}

// ---------------- launch ----------------
extern "C" void kernel_launch(void* const* d_in, const int* in_sizes, int n_in,
                              void* d_out, int out_size){
  const float* q = (const float*)d_in[0];
  const float* k = (const float*)d_in[1];
  const float* v = (const float*)d_in[2];
  const int* wl  = (const int*)d_in[3];
  const int* wr  = (const int*)d_in[4];
  float* out = (float*)d_out;

  cudaFuncSetAttribute(attn_kernel, cudaFuncAttributeMaxDynamicSharedMemorySize, SMEM_TOTAL);

  pre_k0<<<dim3(16, BB*HH), 256>>>(k, v);
  pre_k2<<<dim3(64, BB*HH), 256>>>(k, v);
  attn_kernel<<<dim3(SS/64, BB*HH), 128, SMEM_TOTAL>>>(q, wl, wr, out);
}

// round 8
// speedup vs baseline: 1.1774x; 1.1774x over previous
#include <cuda_runtime.h>
#include <cuda_fp16.h>
#include <math.h>
#include <stdint.h>

#define BB 2
#define SS 2048
#define HH 16
#define DD 128
#define HID (HH*DD)
#define SM_SCALE_L2E 0.12751649736230442f   /* (1/sqrt(128)) * log2(e) */

// ---------------- scratch (no allocation allowed) ----------------
__device__ signed char g_q8[(size_t)BB*HH*SS*DD];
__device__ signed char g_k8[(size_t)BB*HH*SS*DD];
__device__ __half      g_v16[(size_t)BB*HH*SS*DD];
__device__ float g_qscale[BB*HH*(SS/32)];
__device__ float g_kscale[BB*HH*(SS/64)];
__device__ float g_vmean[BB*HH*DD];
__device__ float g_kpart[BB*HH*32*DD];
__device__ float g_vpart[BB*HH*32*DD];

// ---------------- block absmax (256 threads / 8 warps) ----------------
__device__ __forceinline__ float block_absmax(float v, float* red){
  #pragma unroll
  for (int o = 16; o > 0; o >>= 1)
    v = fmaxf(v, __shfl_xor_sync(0xffffffffu, v, o));
  int w = threadIdx.x >> 5;
  if ((threadIdx.x & 31) == 0) red[w] = v;
  __syncthreads();
  float r = red[0];
  #pragma unroll
  for (int i = 1; i < 8; i++) r = fmaxf(r, red[i]);
  return r;
}

// ---------------- K0: mean partials (bx<16) + quant_q (bx>=16) ----------------
__global__ void __launch_bounds__(256)
pre_k0(const float* __restrict__ q, const float* __restrict__ k, const float* __restrict__ v){
  int bh = blockIdx.y, bx = blockIdx.x;
  int b = bh >> 4, h = bh & 15;
  int t = threadIdx.x;
  if (bx < 16){
    int d = t & 127, hf = t >> 7;
    size_t base = ((size_t)b*SS + (size_t)bx*128 + (size_t)hf*64)*HID + h*DD + d;
    float ka = 0.f, va = 0.f;
    #pragma unroll 8
    for (int r2 = 0; r2 < 64; r2++){
      ka += k[base + (size_t)r2*HID];
      va += v[base + (size_t)r2*HID];
    }
    g_kpart[((bh*16 + bx)*2 + hf)*DD + d] = ka;
    g_vpart[((bh*16 + bx)*2 + hf)*DD + d] = va;
  } else {
    __shared__ float red[8];
    int g = bx - 16;                      // 32-row group
    size_t inbase = ((size_t)b*SS + (size_t)g*32)*HID + h*DD;
    float4 vals[4]; float amax = 0.f;
    #pragma unroll
    for (int i = 0; i < 4; i++){
      int f4 = t + i*256;
      int row = f4 >> 5, c4 = f4 & 31;
      float4 x = *(const float4*)(q + inbase + (size_t)row*HID + c4*4);
      vals[i] = x;
      amax = fmaxf(amax, fmaxf(fmaxf(fabsf(x.x), fabsf(x.y)), fmaxf(fabsf(x.z), fabsf(x.w))));
    }
    amax = block_absmax(amax, red);
    float scale = fmaxf(amax / 127.0f, 1e-8f);
    size_t obase = ((size_t)bh*SS + (size_t)g*32)*DD;
    #pragma unroll
    for (int i = 0; i < 4; i++){
      int f4 = t + i*256;
      int row = f4 >> 5, c4 = f4 & 31;
      char4 o;
      o.x = (signed char)(int)fminf(fmaxf(rintf(vals[i].x / scale), -127.f), 127.f);
      o.y = (signed char)(int)fminf(fmaxf(rintf(vals[i].y / scale), -127.f), 127.f);
      o.z = (signed char)(int)fminf(fmaxf(rintf(vals[i].z / scale), -127.f), 127.f);
      o.w = (signed char)(int)fminf(fmaxf(rintf(vals[i].w / scale), -127.f), 127.f);
      *(char4*)(g_q8 + obase + (size_t)row*DD + c4*4) = o;
    }
    if (t == 0) g_qscale[bh*64 + g] = scale;
  }
}

// ---------------- K1: quant_k (bx<32) + smooth_v (bx>=32); means in-block ----------------
__global__ void __launch_bounds__(256)
pre_k2(const float* __restrict__ k, const float* __restrict__ v){
  __shared__ float smean[128];
  int bh = blockIdx.y, bx = blockIdx.x;
  int b = bh >> 4, h = bh & 15;
  int t = threadIdx.x;
  if (t < 128){
    const float* part = (bx < 32) ? g_kpart : g_vpart;
    float a = 0.f;
    #pragma unroll
    for (int c = 0; c < 32; c++) a += part[(bh*32 + c)*DD + t];
    smean[t] = a / (float)SS;
    if (bx >= 32) g_vmean[bh*DD + t] = smean[t];
  }
  __syncthreads();
  if (bx < 32){
    __shared__ float red[8];
    int g = bx;
    size_t inbase = ((size_t)b*SS + (size_t)g*64)*HID + h*DD;
    float4 vals[8]; float amax = 0.f;
    #pragma unroll
    for (int i = 0; i < 8; i++){
      int f4 = t + i*256;
      int row = f4 >> 5, c4 = f4 & 31;
      float4 x = *(const float4*)(k + inbase + (size_t)row*HID + c4*4);
      x.x -= smean[c4*4]; x.y -= smean[c4*4+1]; x.z -= smean[c4*4+2]; x.w -= smean[c4*4+3];
      vals[i] = x;
      amax = fmaxf(amax, fmaxf(fmaxf(fabsf(x.x), fabsf(x.y)), fmaxf(fabsf(x.z), fabsf(x.w))));
    }
    amax = block_absmax(amax, red);
    float scale = fmaxf(amax / 127.0f, 1e-8f);
    size_t obase = ((size_t)bh*SS + (size_t)g*64)*DD;
    #pragma unroll
    for (int i = 0; i < 8; i++){
      int f4 = t + i*256;
      int row = f4 >> 5, c4 = f4 & 31;
      char4 o;
      o.x = (signed char)(int)fminf(fmaxf(rintf(vals[i].x / scale), -127.f), 127.f);
      o.y = (signed char)(int)fminf(fmaxf(rintf(vals[i].y / scale), -127.f), 127.f);
      o.z = (signed char)(int)fminf(fmaxf(rintf(vals[i].z / scale), -127.f), 127.f);
      o.w = (signed char)(int)fminf(fmaxf(rintf(vals[i].w / scale), -127.f), 127.f);
      *(char4*)(g_k8 + obase + (size_t)row*DD + c4*4) = o;
    }
    if (t == 0) g_kscale[bh*32 + g] = scale;
  } else {
    int g = bx - 32;
    size_t inbase = ((size_t)b*SS + (size_t)g*64)*HID + h*DD;
    size_t obase  = ((size_t)bh*SS + (size_t)g*64)*DD;
    #pragma unroll
    for (int i = 0; i < 8; i++){
      int f4 = t + i*256;
      int row = f4 >> 5, c4 = f4 & 31;
      float4 x = *(const float4*)(v + inbase + (size_t)row*HID + c4*4);
      __half2 h0 = __floats2half2_rn(x.x - smean[c4*4],   x.y - smean[c4*4+1]);
      __half2 h1 = __floats2half2_rn(x.z - smean[c4*4+2], x.w - smean[c4*4+3]);
      uint2 o; o.x = *(uint32_t*)&h0; o.y = *(uint32_t*)&h1;
      *(uint2*)(g_v16 + obase + (size_t)row*DD + c4*4) = o;
    }
  }
}

// ---------------- MMA helpers ----------------
__device__ __forceinline__ void mma16816(float c[4], const uint32_t a[4], uint32_t b0, uint32_t b1){
  asm volatile(
    "mma.sync.aligned.m16n8k16.row.col.f32.f16.f16.f32 "
    "{%0,%1,%2,%3}, {%4,%5,%6,%7}, {%8,%9}, {%0,%1,%2,%3};\n"
    : "+f"(c[0]), "+f"(c[1]), "+f"(c[2]), "+f"(c[3])
    : "r"(a[0]), "r"(a[1]), "r"(a[2]), "r"(a[3]), "r"(b0), "r"(b1));
}
__device__ __forceinline__ void mma_s8(int c[4], const uint32_t a[4], uint32_t b0, uint32_t b1){
  asm volatile(
    "mma.sync.aligned.m16n8k32.row.col.s32.s8.s8.s32 "
    "{%0,%1,%2,%3}, {%4,%5,%6,%7}, {%8,%9}, {%0,%1,%2,%3};\n"
    : "+r"(c[0]), "+r"(c[1]), "+r"(c[2]), "+r"(c[3])
    : "r"(a[0]), "r"(a[1]), "r"(a[2]), "r"(a[3]), "r"(b0), "r"(b1));
}
__device__ __forceinline__ void ldmx4(uint32_t& t0, uint32_t& t1, uint32_t& t2, uint32_t& t3, uint32_t addr){
  asm volatile("ldmatrix.sync.aligned.m8n8.x4.shared.b16 {%0,%1,%2,%3}, [%4];\n"
    : "=r"(t0), "=r"(t1), "=r"(t2), "=r"(t3) : "r"(addr));
}
__device__ __forceinline__ void ldmx4t(uint32_t& t0, uint32_t& t1, uint32_t& t2, uint32_t& t3, uint32_t addr){
  asm volatile("ldmatrix.sync.aligned.m8n8.x4.trans.shared.b16 {%0,%1,%2,%3}, [%4];\n"
    : "=r"(t0), "=r"(t1), "=r"(t2), "=r"(t3) : "r"(addr));
}
__device__ __forceinline__ void stg_cs_f2(float* p, float2 v){
  asm volatile("st.global.cs.v2.f32 [%0], {%1,%2};\n" :: "l"(p), "f"(v.x), "f"(v.y) : "memory");
}
#define CP16(dst, src) asm volatile("cp.async.cg.shared.global [%0], [%1], 16;\n" :: "r"(dst), "l"(src) : "memory")

#define KPITCH 144
#define VPITCH 272
#define SK_OFF(st) ((st)*64*KPITCH)
#define SV_OFF(st) (2*64*KPITCH + (st)*64*VPITCH)
#define SMEM_TOTAL (2*64*KPITCH + 2*64*VPITCH)   // 53248

// ---------------- main attention kernel ----------------
__global__ void __launch_bounds__(128, 3)
attn_kernel(const int* __restrict__ wlp, const int* __restrict__ wrp, float* __restrict__ out){
  extern __shared__ char smem[];
  const uint32_t smem_b = (uint32_t)__cvta_generic_to_shared(smem);

  // work-descending q-tile order: interior tiles first
  const int bx = blockIdx.x;
  const int xq = (bx & 1) ? (16 + (bx >> 1)) : (15 - (bx >> 1));
  const int i0  = xq * 64;
  const int bh  = blockIdx.y;
  const int b   = bh >> 4, h = bh & 15;
  const int tid = threadIdx.x, wid = tid >> 5, lane = tid & 31;
  const int r   = lane >> 2, q2 = (lane & 3) * 2, c4 = (lane & 3) * 4;
  const int wl = *wlp, wr = *wrp;

  const signed char* Qg = g_q8 + ((size_t)bh*SS + i0)*DD;
  const signed char* Kg = g_k8 + (size_t)bh*SS*DD;
  const __half*      Vg = g_v16 + (size_t)bh*SS*DD;

  // --- stage Q into stage-0 K region, build int8 A-fragments ---
  {
    char* sQ = smem;
    #pragma unroll
    for (int it = tid; it < 512; it += 128){
      int row = it >> 3, seg = it & 7;
      *(uint4*)(sQ + row*KPITCH + seg*16) = *(const uint4*)(Qg + row*128 + seg*16);
    }
  }
  __syncthreads();
  const int qrow = wid*16 + r;
  uint32_t afrag[4][4];
  #pragma unroll
  for (int kc = 0; kc < 4; kc++){
    const char* sQ = smem;
    afrag[kc][0] = *(const uint32_t*)(sQ + (qrow  )*KPITCH + kc*32 + c4     );
    afrag[kc][1] = *(const uint32_t*)(sQ + (qrow+8)*KPITCH + kc*32 + c4     );
    afrag[kc][2] = *(const uint32_t*)(sQ + (qrow  )*KPITCH + kc*32 + c4 + 16);
    afrag[kc][3] = *(const uint32_t*)(sQ + (qrow+8)*KPITCH + kc*32 + c4 + 16);
  }
  __syncthreads();

  const float qsl = g_qscale[bh*(SS/32) + ((i0 + wid*16) >> 5)] * SM_SCALE_L2E;
  const int i_r0 = i0 + qrow, i_r1 = i_r0 + 8;
  const int lo0 = (wl < 0) ? -0x40000000 : i_r0 - wl;
  const int hi0 = (wr < 0) ?  0x40000000 : i_r0 + wr;
  const int lo1 = (wl < 0) ? -0x40000000 : i_r1 - wl;
  const int hi1 = (wr < 0) ?  0x40000000 : i_r1 + wr;

  float of[16][4];
  #pragma unroll
  for (int n = 0; n < 16; n++){ of[n][0]=0.f; of[n][1]=0.f; of[n][2]=0.f; of[n][3]=0.f; }
  float m0 = -1e30f, m1 = -1e30f, l0 = 0.f, l1 = 0.f;

  int jlo = (wl >= 0) ? max(0, i0 - wl) : 0;
  int jhi = (wr >= 0) ? min(SS-1, i0 + 63 + wr) : SS-1;
  const int jloT = jlo & ~63;
  const int nt = ((jhi - jloT) >> 6) + 1;

  auto issue = [&](int st, int j0){
    uint32_t kb = smem_b + SK_OFF(st);
    const signed char* kg = Kg + (size_t)j0*128;
    #pragma unroll
    for (int c = tid; c < 512; c += 128){
      int row = c >> 3, seg = c & 7;
      CP16(kb + row*KPITCH + seg*16, kg + row*128 + seg*16);
    }
    uint32_t vb = smem_b + SV_OFF(st);
    const __half* vg = Vg + (size_t)j0*128;
    #pragma unroll
    for (int c = tid; c < 1024; c += 128){
      int row = c >> 4, seg = c & 15;
      CP16(vb + row*VPITCH + seg*16, (const char*)vg + row*256 + seg*16);
    }
    asm volatile("cp.async.commit_group;\n" ::: "memory");
  };

  issue(0, jloT);

  const int ldm_g = lane >> 3;
  const uint32_t kfrag_off = (uint32_t)(((ldm_g >> 1)*8 + (lane & 7))*KPITCH + (ldm_g & 1)*16);

  float ksc = g_kscale[bh*(SS/64) + (jloT >> 6)];   // prefetched scale for tile 0

  for (int it = 0; it < nt; it++){
    const int j0 = jloT + it*64;
    const int st = it & 1;
    if (it + 1 < nt){
      issue(st ^ 1, j0 + 64);
      asm volatile("cp.async.wait_group 1;\n" ::: "memory");
    } else {
      asm volatile("cp.async.wait_group 0;\n" ::: "memory");
    }
    __syncthreads();

    const float dq = qsl * ksc;
    if (it + 1 < nt) ksc = g_kscale[bh*(SS/64) + ((j0 + 64) >> 6)];  // prefetch next

    // --- S = Q K^T (int8 MMA, exact); B-frags via ldmatrix.x4 ---
    int acc[8][4];
    #pragma unroll
    for (int n = 0; n < 8; n++){ acc[n][0]=0; acc[n][1]=0; acc[n][2]=0; acc[n][3]=0; }
    const uint32_t kfb = smem_b + SK_OFF(st) + kfrag_off;
    #pragma unroll
    for (int m = 0; m < 16; m++){
      const int kc = m >> 2, nfp = m & 3;
      uint32_t b0, b1, b2, b3;
      ldmx4(b0, b1, b2, b3, kfb + nfp*(16*KPITCH) + kc*32);
      mma_s8(acc[nfp*2    ], afrag[kc], b0, b1);
      mma_s8(acc[nfp*2 + 1], afrag[kc], b2, b3);
    }

    // --- dequant (base-2 domain) + mask; fast path for interior tiles ---
    float sf[8][4];
    const bool full = ((wl < 0) || (j0 >= i0 + 63 - wl)) && ((wr < 0) || (j0 + 63 <= i0 + wr));
    if (full){
      #pragma unroll
      for (int nf = 0; nf < 8; nf++){
        sf[nf][0] = __int2float_rn(acc[nf][0]) * dq;
        sf[nf][1] = __int2float_rn(acc[nf][1]) * dq;
        sf[nf][2] = __int2float_rn(acc[nf][2]) * dq;
        sf[nf][3] = __int2float_rn(acc[nf][3]) * dq;
      }
    } else {
      #pragma unroll
      for (int nf = 0; nf < 8; nf++){
        int jc = j0 + nf*8 + q2;
        sf[nf][0] = (jc   >= lo0 && jc   <= hi0) ? __int2float_rn(acc[nf][0]) * dq : -INFINITY;
        sf[nf][1] = (jc+1 >= lo0 && jc+1 <= hi0) ? __int2float_rn(acc[nf][1]) * dq : -INFINITY;
        sf[nf][2] = (jc   >= lo1 && jc   <= hi1) ? __int2float_rn(acc[nf][2]) * dq : -INFINITY;
        sf[nf][3] = (jc+1 >= lo1 && jc+1 <= hi1) ? __int2float_rn(acc[nf][3]) * dq : -INFINITY;
      }
    }
    // pairwise max trees (short critical path)
    float mA0[4], mA1[4];
    #pragma unroll
    for (int p = 0; p < 4; p++){
      mA0[p] = fmaxf(fmaxf(sf[2*p][0], sf[2*p][1]), fmaxf(sf[2*p+1][0], sf[2*p+1][1]));
      mA1[p] = fmaxf(fmaxf(sf[2*p][2], sf[2*p][3]), fmaxf(sf[2*p+1][2], sf[2*p+1][3]));
    }
    float mt0 = fmaxf(fmaxf(mA0[0], mA0[1]), fmaxf(mA0[2], mA0[3]));
    float mt1 = fmaxf(fmaxf(mA1[0], mA1[1]), fmaxf(mA1[2], mA1[3]));
    mt0 = fmaxf(mt0, __shfl_xor_sync(0xffffffffu, mt0, 1));
    mt0 = fmaxf(mt0, __shfl_xor_sync(0xffffffffu, mt0, 2));
    mt1 = fmaxf(mt1, __shfl_xor_sync(0xffffffffu, mt1, 1));
    mt1 = fmaxf(mt1, __shfl_xor_sync(0xffffffffu, mt1, 2));

    const bool raise = (mt0 > m0) || (mt1 > m1);
    float mn0 = fmaxf(m0, mt0), mn1 = fmaxf(m1, mt1);
    float a0 = exp2f(m0 - mn0), a1 = exp2f(m1 - mn1);
    #pragma unroll
    for (int nf = 0; nf < 8; nf++){
      sf[nf][0] = exp2f(sf[nf][0] - mn0);
      sf[nf][1] = exp2f(sf[nf][1] - mn0);
      sf[nf][2] = exp2f(sf[nf][2] - mn1);
      sf[nf][3] = exp2f(sf[nf][3] - mn1);
    }
    // pairwise sum trees
    float t0A[4], t1A[4];
    #pragma unroll
    for (int p = 0; p < 4; p++){
      t0A[p] = (sf[2*p][0] + sf[2*p][1]) + (sf[2*p+1][0] + sf[2*p+1][1]);
      t1A[p] = (sf[2*p][2] + sf[2*p][3]) + (sf[2*p+1][2] + sf[2*p+1][3]);
    }
    float t0 = (t0A[0] + t0A[1]) + (t0A[2] + t0A[3]);
    float t1 = (t1A[0] + t1A[1]) + (t1A[2] + t1A[3]);
    l0 = l0*a0 + t0; l1 = l1*a1 + t1;
    m0 = mn0; m1 = mn1;
    if (__ballot_sync(0xffffffffu, raise)){
      #pragma unroll
      for (int n = 0; n < 16; n++){
        of[n][0]*=a0; of[n][1]*=a0; of[n][2]*=a1; of[n][3]*=a1;
      }
    }

    // --- pack P to f16 A-fragments ---
    uint32_t pfrag[4][4];
    #pragma unroll
    for (int kc = 0; kc < 4; kc++){
      __half2 p0 = __floats2half2_rn(sf[2*kc  ][0], sf[2*kc  ][1]);
      __half2 p1 = __floats2half2_rn(sf[2*kc  ][2], sf[2*kc  ][3]);
      __half2 p2 = __floats2half2_rn(sf[2*kc+1][0], sf[2*kc+1][1]);
      __half2 p3 = __floats2half2_rn(sf[2*kc+1][2], sf[2*kc+1][3]);
      pfrag[kc][0] = *(uint32_t*)&p0; pfrag[kc][1] = *(uint32_t*)&p1;
      pfrag[kc][2] = *(uint32_t*)&p2; pfrag[kc][3] = *(uint32_t*)&p3;
    }

    // --- O += P V : V^T fragments via ldmatrix.trans ---
    const uint32_t svb = smem_b + SV_OFF(st);
    const int jrow = lane & 15;
    const int dsel = (lane & 16) ? 8 : 0;
    #pragma unroll
    for (int jc = 0; jc < 4; jc++){
      #pragma unroll
      for (int dc = 0; dc < 8; dc++){
        uint32_t addr = svb + (jc*16 + jrow)*VPITCH + (dc*16 + dsel)*2;
        uint32_t v0, v1, v2, v3;
        ldmx4t(v0, v1, v2, v3, addr);
        mma16816(of[dc*2    ], pfrag[jc], v0, v1);
        mma16816(of[dc*2 + 1], pfrag[jc], v2, v3);
      }
    }
    __syncthreads();
  }

  // --- epilogue: reduce l over quad, normalize, f16-round, add v_mean ---
  l0 += __shfl_xor_sync(0xffffffffu, l0, 1);
  l0 += __shfl_xor_sync(0xffffffffu, l0, 2);
  l1 += __shfl_xor_sync(0xffffffffu, l1, 1);
  l1 += __shfl_xor_sync(0xffffffffu, l1, 2);
  float inv0 = 1.0f / l0, inv1 = 1.0f / l1;
  float* ob = out + ((size_t)b*SS)*HID + h*DD;
  const float* vm = g_vmean + bh*DD;
  #pragma unroll
  for (int n = 0; n < 16; n++){
    int d0 = n*8 + q2;
    float2 o0, o1;
    o0.x = __half2float(__float2half_rn(of[n][0]*inv0)) + vm[d0];
    o0.y = __half2float(__float2half_rn(of[n][1]*inv0)) + vm[d0+1];
    o1.x = __half2float(__float2half_rn(of[n][2]*inv1)) + vm[d0];
    o1.y = __half2float(__float2half_rn(of[n][3]*inv1)) + vm[d0+1];
    stg_cs_f2(ob + (size_t)i_r0*HID + d0, o0);
    stg_cs_f2(ob + (size_t)i_r1*HID + d0, o1);
  }
}

// ---------------- launch ----------------
extern "C" void kernel_launch(void* const* d_in, const int* in_sizes, int n_in,
                              void* d_out, int out_size){
  const float* q = (const float*)d_in[0];
  const float* k = (const float*)d_in[1];
  const float* v = (const float*)d_in[2];
  const int* wl  = (const int*)d_in[3];
  const int* wr  = (const int*)d_in[4];
  float* out = (float*)d_out;

  cudaFuncSetAttribute(attn_kernel, cudaFuncAttributeMaxDynamicSharedMemorySize, SMEM_TOTAL);

  pre_k0<<<dim3(80, BB*HH), 256>>>(q, k, v);
  pre_k2<<<dim3(64, BB*HH), 256>>>(k, v);
  attn_kernel<<<dim3(SS/64, BB*HH), 128, SMEM_TOTAL>>>(wl, wr, out);
}

// round 9
// speedup vs baseline: 1.2237x; 1.0393x over previous
#include <cuda_runtime.h>
#include <cuda_fp16.h>
#include <math.h>
#include <stdint.h>

#define BB 2
#define SS 2048
#define HH 16
#define DD 128
#define HID (HH*DD)
#define SM_SCALE_L2E 0.12751649736230442f   /* (1/sqrt(128)) * log2(e) */
#define ATTN_GRID 444
#define N_ITEMS 1024

// ---------------- scratch (no allocation allowed) ----------------
__device__ signed char g_q8[(size_t)BB*HH*SS*DD];
__device__ signed char g_k8[(size_t)BB*HH*SS*DD];
__device__ __half      g_v16[(size_t)BB*HH*SS*DD];
__device__ float g_qscale[BB*HH*(SS/32)];
__device__ float g_kscale[BB*HH*(SS/64)];
__device__ float g_vmean[BB*HH*DD];
__device__ float g_kpart[BB*HH*32*DD];
__device__ float g_vpart[BB*HH*32*DD];
__device__ int   g_wq;

// ---------------- block absmax (256 threads / 8 warps) ----------------
__device__ __forceinline__ float block_absmax(float v, float* red){
  #pragma unroll
  for (int o = 16; o > 0; o >>= 1)
    v = fmaxf(v, __shfl_xor_sync(0xffffffffu, v, o));
  int w = threadIdx.x >> 5;
  if ((threadIdx.x & 31) == 0) red[w] = v;
  __syncthreads();
  float r = red[0];
  #pragma unroll
  for (int i = 1; i < 8; i++) r = fmaxf(r, red[i]);
  return r;
}

// ---------------- K0: mean partials (bx<16) + quant_q (bx>=16) ----------------
__global__ void __launch_bounds__(256)
pre_k0(const float* __restrict__ q, const float* __restrict__ k, const float* __restrict__ v){
  int bh = blockIdx.y, bx = blockIdx.x;
  int b = bh >> 4, h = bh & 15;
  int t = threadIdx.x;
  if (bx == 0 && bh == 0 && t == 0) g_wq = ATTN_GRID;   // reset work queue every replay
  if (bx < 16){
    int d = t & 127, hf = t >> 7;
    size_t base = ((size_t)b*SS + (size_t)bx*128 + (size_t)hf*64)*HID + h*DD + d;
    float ka = 0.f, va = 0.f;
    #pragma unroll 8
    for (int r2 = 0; r2 < 64; r2++){
      ka += k[base + (size_t)r2*HID];
      va += v[base + (size_t)r2*HID];
    }
    g_kpart[((bh*16 + bx)*2 + hf)*DD + d] = ka;
    g_vpart[((bh*16 + bx)*2 + hf)*DD + d] = va;
  } else {
    __shared__ float red[8];
    int g = bx - 16;                      // 32-row group
    size_t inbase = ((size_t)b*SS + (size_t)g*32)*HID + h*DD;
    float4 vals[4]; float amax = 0.f;
    #pragma unroll
    for (int i = 0; i < 4; i++){
      int f4 = t + i*256;
      int row = f4 >> 5, c4 = f4 & 31;
      float4 x = *(const float4*)(q + inbase + (size_t)row*HID + c4*4);
      vals[i] = x;
      amax = fmaxf(amax, fmaxf(fmaxf(fabsf(x.x), fabsf(x.y)), fmaxf(fabsf(x.z), fabsf(x.w))));
    }
    amax = block_absmax(amax, red);
    float scale = fmaxf(amax / 127.0f, 1e-8f);
    size_t obase = ((size_t)bh*SS + (size_t)g*32)*DD;
    #pragma unroll
    for (int i = 0; i < 4; i++){
      int f4 = t + i*256;
      int row = f4 >> 5, c4 = f4 & 31;
      char4 o;
      o.x = (signed char)(int)fminf(fmaxf(rintf(vals[i].x / scale), -127.f), 127.f);
      o.y = (signed char)(int)fminf(fmaxf(rintf(vals[i].y / scale), -127.f), 127.f);
      o.z = (signed char)(int)fminf(fmaxf(rintf(vals[i].z / scale), -127.f), 127.f);
      o.w = (signed char)(int)fminf(fmaxf(rintf(vals[i].w / scale), -127.f), 127.f);
      *(char4*)(g_q8 + obase + (size_t)row*DD + c4*4) = o;
    }
    if (t == 0) g_qscale[bh*64 + g] = scale;
  }
}

// ---------------- K1: quant_k (bx<32) + smooth_v (bx>=32); means in-block ----------------
__global__ void __launch_bounds__(256)
pre_k2(const float* __restrict__ k, const float* __restrict__ v){
  __shared__ float smean[128];
  int bh = blockIdx.y, bx = blockIdx.x;
  int b = bh >> 4, h = bh & 15;
  int t = threadIdx.x;
  if (t < 128){
    const float* part = (bx < 32) ? g_kpart : g_vpart;
    float a = 0.f;
    #pragma unroll
    for (int c = 0; c < 32; c++) a += part[(bh*32 + c)*DD + t];
    smean[t] = a / (float)SS;
    if (bx >= 32) g_vmean[bh*DD + t] = smean[t];
  }
  __syncthreads();
  if (bx < 32){
    __shared__ float red[8];
    int g = bx;
    size_t inbase = ((size_t)b*SS + (size_t)g*64)*HID + h*DD;
    float4 vals[8]; float amax = 0.f;
    #pragma unroll
    for (int i = 0; i < 8; i++){
      int f4 = t + i*256;
      int row = f4 >> 5, c4 = f4 & 31;
      float4 x = *(const float4*)(k + inbase + (size_t)row*HID + c4*4);
      x.x -= smean[c4*4]; x.y -= smean[c4*4+1]; x.z -= smean[c4*4+2]; x.w -= smean[c4*4+3];
      vals[i] = x;
      amax = fmaxf(amax, fmaxf(fmaxf(fabsf(x.x), fabsf(x.y)), fmaxf(fabsf(x.z), fabsf(x.w))));
    }
    amax = block_absmax(amax, red);
    float scale = fmaxf(amax / 127.0f, 1e-8f);
    size_t obase = ((size_t)bh*SS + (size_t)g*64)*DD;
    #pragma unroll
    for (int i = 0; i < 8; i++){
      int f4 = t + i*256;
      int row = f4 >> 5, c4 = f4 & 31;
      char4 o;
      o.x = (signed char)(int)fminf(fmaxf(rintf(vals[i].x / scale), -127.f), 127.f);
      o.y = (signed char)(int)fminf(fmaxf(rintf(vals[i].y / scale), -127.f), 127.f);
      o.z = (signed char)(int)fminf(fmaxf(rintf(vals[i].z / scale), -127.f), 127.f);
      o.w = (signed char)(int)fminf(fmaxf(rintf(vals[i].w / scale), -127.f), 127.f);
      *(char4*)(g_k8 + obase + (size_t)row*DD + c4*4) = o;
    }
    if (t == 0) g_kscale[bh*32 + g] = scale;
  } else {
    int g = bx - 32;
    size_t inbase = ((size_t)b*SS + (size_t)g*64)*HID + h*DD;
    size_t obase  = ((size_t)bh*SS + (size_t)g*64)*DD;
    #pragma unroll
    for (int i = 0; i < 8; i++){
      int f4 = t + i*256;
      int row = f4 >> 5, c4 = f4 & 31;
      float4 x = *(const float4*)(v + inbase + (size_t)row*HID + c4*4);
      __half2 h0 = __floats2half2_rn(x.x - smean[c4*4],   x.y - smean[c4*4+1]);
      __half2 h1 = __floats2half2_rn(x.z - smean[c4*4+2], x.w - smean[c4*4+3]);
      uint2 o; o.x = *(uint32_t*)&h0; o.y = *(uint32_t*)&h1;
      *(uint2*)(g_v16 + obase + (size_t)row*DD + c4*4) = o;
    }
  }
}

// ---------------- MMA helpers ----------------
__device__ __forceinline__ void mma16816(float c[4], const uint32_t a[4], uint32_t b0, uint32_t b1){
  asm volatile(
    "mma.sync.aligned.m16n8k16.row.col.f32.f16.f16.f32 "
    "{%0,%1,%2,%3}, {%4,%5,%6,%7}, {%8,%9}, {%0,%1,%2,%3};\n"
    : "+f"(c[0]), "+f"(c[1]), "+f"(c[2]), "+f"(c[3])
    : "r"(a[0]), "r"(a[1]), "r"(a[2]), "r"(a[3]), "r"(b0), "r"(b1));
}
__device__ __forceinline__ void mma_s8(int c[4], const uint32_t a[4], uint32_t b0, uint32_t b1){
  asm volatile(
    "mma.sync.aligned.m16n8k32.row.col.s32.s8.s8.s32 "
    "{%0,%1,%2,%3}, {%4,%5,%6,%7}, {%8,%9}, {%0,%1,%2,%3};\n"
    : "+r"(c[0]), "+r"(c[1]), "+r"(c[2]), "+r"(c[3])
    : "r"(a[0]), "r"(a[1]), "r"(a[2]), "r"(a[3]), "r"(b0), "r"(b1));
}
__device__ __forceinline__ void ldmx4(uint32_t& t0, uint32_t& t1, uint32_t& t2, uint32_t& t3, uint32_t addr){
  asm volatile("ldmatrix.sync.aligned.m8n8.x4.shared.b16 {%0,%1,%2,%3}, [%4];\n"
    : "=r"(t0), "=r"(t1), "=r"(t2), "=r"(t3) : "r"(addr));
}
__device__ __forceinline__ void ldmx4t(uint32_t& t0, uint32_t& t1, uint32_t& t2, uint32_t& t3, uint32_t addr){
  asm volatile("ldmatrix.sync.aligned.m8n8.x4.trans.shared.b16 {%0,%1,%2,%3}, [%4];\n"
    : "=r"(t0), "=r"(t1), "=r"(t2), "=r"(t3) : "r"(addr));
}
#define CP16(dst, src) asm volatile("cp.async.cg.shared.global [%0], [%1], 16;\n" :: "r"(dst), "l"(src) : "memory")

#define KPITCH 144
#define VPITCH 272
#define SK_OFF(st) ((st)*64*KPITCH)
#define SV_OFF(st) (2*64*KPITCH + (st)*64*VPITCH)
#define SMEM_TOTAL (2*64*KPITCH + 2*64*VPITCH)   // 53248

// ---------------- main attention kernel (persistent, dynamic queue) ----------------
__global__ void __launch_bounds__(128, 3)
attn_kernel(const int* __restrict__ wlp, const int* __restrict__ wrp, float* __restrict__ out){
  extern __shared__ char smem[];
  __shared__ int s_next;
  const uint32_t smem_b = (uint32_t)__cvta_generic_to_shared(smem);

  const int tid = threadIdx.x, wid = tid >> 5, lane = tid & 31;
  const int r   = lane >> 2, q2 = (lane & 3) * 2, c4 = (lane & 3) * 4;
  const int wl = *wlp, wr = *wrp;
  const int ldm_g = lane >> 3;
  const uint32_t kfrag_off = (uint32_t)(((ldm_g >> 1)*8 + (lane & 7))*KPITCH + (ldm_g & 1)*16);
  const int jrow = lane & 15;
  const int dsel = (lane & 16) ? 8 : 0;
  const int qrow = wid*16 + r;

  int wi = blockIdx.x;
  while (wi < N_ITEMS){
    // work item -> (q-tile, bh); largest-work items have smallest index (LPT order)
    const int q_ord = wi >> 5;
    const int bh = wi & 31;
    const int xq = (q_ord & 1) ? (16 + (q_ord >> 1)) : (15 - (q_ord >> 1));
    const int i0 = xq * 64;
    const int b = bh >> 4, h = bh & 15;

    const signed char* Qg = g_q8 + ((size_t)bh*SS + i0)*DD;
    const signed char* Kg = g_k8 + (size_t)bh*SS*DD;
    const __half*      Vg = g_v16 + (size_t)bh*SS*DD;

    // --- stage Q into stage-0 K region, build int8 A-fragments ---
    {
      char* sQ = smem;
      #pragma unroll
      for (int it = tid; it < 512; it += 128){
        int row = it >> 3, seg = it & 7;
        *(uint4*)(sQ + row*KPITCH + seg*16) = *(const uint4*)(Qg + row*128 + seg*16);
      }
    }
    __syncthreads();
    uint32_t afrag[4][4];
    #pragma unroll
    for (int kc = 0; kc < 4; kc++){
      const char* sQ = smem;
      afrag[kc][0] = *(const uint32_t*)(sQ + (qrow  )*KPITCH + kc*32 + c4     );
      afrag[kc][1] = *(const uint32_t*)(sQ + (qrow+8)*KPITCH + kc*32 + c4     );
      afrag[kc][2] = *(const uint32_t*)(sQ + (qrow  )*KPITCH + kc*32 + c4 + 16);
      afrag[kc][3] = *(const uint32_t*)(sQ + (qrow+8)*KPITCH + kc*32 + c4 + 16);
    }
    __syncthreads();

    const float qsl = g_qscale[bh*(SS/32) + ((i0 + wid*16) >> 5)] * SM_SCALE_L2E;
    const int i_r0 = i0 + qrow, i_r1 = i_r0 + 8;
    const int lo0 = (wl < 0) ? -0x40000000 : i_r0 - wl;
    const int hi0 = (wr < 0) ?  0x40000000 : i_r0 + wr;
    const int lo1 = (wl < 0) ? -0x40000000 : i_r1 - wl;
    const int hi1 = (wr < 0) ?  0x40000000 : i_r1 + wr;

    float of[16][4];
    #pragma unroll
    for (int n = 0; n < 16; n++){ of[n][0]=0.f; of[n][1]=0.f; of[n][2]=0.f; of[n][3]=0.f; }
    float m0 = -1e30f, m1 = -1e30f, l0 = 0.f, l1 = 0.f;

    int jlo = (wl >= 0) ? max(0, i0 - wl) : 0;
    int jhi = (wr >= 0) ? min(SS-1, i0 + 63 + wr) : SS-1;
    const int jloT = jlo & ~63;
    const int nt = ((jhi - jloT) >> 6) + 1;

    auto issue = [&](int st, int j0){
      uint32_t kb = smem_b + SK_OFF(st);
      const signed char* kg = Kg + (size_t)j0*128;
      #pragma unroll
      for (int c = tid; c < 512; c += 128){
        int row = c >> 3, seg = c & 7;
        CP16(kb + row*KPITCH + seg*16, kg + row*128 + seg*16);
      }
      uint32_t vb = smem_b + SV_OFF(st);
      const __half* vg = Vg + (size_t)j0*128;
      #pragma unroll
      for (int c = tid; c < 1024; c += 128){
        int row = c >> 4, seg = c & 15;
        CP16(vb + row*VPITCH + seg*16, (const char*)vg + row*256 + seg*16);
      }
      asm volatile("cp.async.commit_group;\n" ::: "memory");
    };

    issue(0, jloT);
    float ksc = g_kscale[bh*(SS/64) + (jloT >> 6)];

    for (int it = 0; it < nt; it++){
      const int j0 = jloT + it*64;
      const int st = it & 1;
      if (it + 1 < nt){
        issue(st ^ 1, j0 + 64);
        asm volatile("cp.async.wait_group 1;\n" ::: "memory");
      } else {
        asm volatile("cp.async.wait_group 0;\n" ::: "memory");
      }
      __syncthreads();

      const float dq = qsl * ksc;
      if (it + 1 < nt) ksc = g_kscale[bh*(SS/64) + ((j0 + 64) >> 6)];

      // --- S = Q K^T (int8 MMA, exact); B-frags via ldmatrix.x4 ---
      int acc[8][4];
      #pragma unroll
      for (int n = 0; n < 8; n++){ acc[n][0]=0; acc[n][1]=0; acc[n][2]=0; acc[n][3]=0; }
      const uint32_t kfb = smem_b + SK_OFF(st) + kfrag_off;
      #pragma unroll
      for (int m = 0; m < 16; m++){
        const int kc = m >> 2, nfp = m & 3;
        uint32_t b0, b1, b2, b3;
        ldmx4(b0, b1, b2, b3, kfb + nfp*(16*KPITCH) + kc*32);
        mma_s8(acc[nfp*2    ], afrag[kc], b0, b1);
        mma_s8(acc[nfp*2 + 1], afrag[kc], b2, b3);
      }

      // --- softmax: int-domain max + fused exp on interior tiles ---
      const bool full = ((wl < 0) || (j0 >= i0 + 63 - wl)) && ((wr < 0) || (j0 + 63 <= i0 + wr));
      float sf[8][4];
      float mt0, mt1;
      if (full){
        int iA0[4], iA1[4];
        #pragma unroll
        for (int p = 0; p < 4; p++){
          iA0[p] = max(max(acc[2*p][0], acc[2*p][1]), max(acc[2*p+1][0], acc[2*p+1][1]));
          iA1[p] = max(max(acc[2*p][2], acc[2*p][3]), max(acc[2*p+1][2], acc[2*p+1][3]));
        }
        int im0 = max(max(iA0[0], iA0[1]), max(iA0[2], iA0[3]));
        int im1 = max(max(iA1[0], iA1[1]), max(iA1[2], iA1[3]));
        mt0 = __int2float_rn(im0) * dq;
        mt1 = __int2float_rn(im1) * dq;
      } else {
        #pragma unroll
        for (int nf = 0; nf < 8; nf++){
          int jc = j0 + nf*8 + q2;
          sf[nf][0] = (jc   >= lo0 && jc   <= hi0) ? __int2float_rn(acc[nf][0]) * dq : -INFINITY;
          sf[nf][1] = (jc+1 >= lo0 && jc+1 <= hi0) ? __int2float_rn(acc[nf][1]) * dq : -INFINITY;
          sf[nf][2] = (jc   >= lo1 && jc   <= hi1) ? __int2float_rn(acc[nf][2]) * dq : -INFINITY;
          sf[nf][3] = (jc+1 >= lo1 && jc+1 <= hi1) ? __int2float_rn(acc[nf][3]) * dq : -INFINITY;
        }
        float mA0[4], mA1[4];
        #pragma unroll
        for (int p = 0; p < 4; p++){
          mA0[p] = fmaxf(fmaxf(sf[2*p][0], sf[2*p][1]), fmaxf(sf[2*p+1][0], sf[2*p+1][1]));
          mA1[p] = fmaxf(fmaxf(sf[2*p][2], sf[2*p][3]), fmaxf(sf[2*p+1][2], sf[2*p+1][3]));
        }
        mt0 = fmaxf(fmaxf(mA0[0], mA0[1]), fmaxf(mA0[2], mA0[3]));
        mt1 = fmaxf(fmaxf(mA1[0], mA1[1]), fmaxf(mA1[2], mA1[3]));
      }
      mt0 = fmaxf(mt0, __shfl_xor_sync(0xffffffffu, mt0, 1));
      mt0 = fmaxf(mt0, __shfl_xor_sync(0xffffffffu, mt0, 2));
      mt1 = fmaxf(mt1, __shfl_xor_sync(0xffffffffu, mt1, 1));
      mt1 = fmaxf(mt1, __shfl_xor_sync(0xffffffffu, mt1, 2));

      const bool raise = (mt0 > m0) || (mt1 > m1);
      const float mn0 = fmaxf(m0, mt0), mn1 = fmaxf(m1, mt1);
      const float a0 = exp2f(m0 - mn0), a1 = exp2f(m1 - mn1);
      if (full){
        #pragma unroll
        for (int nf = 0; nf < 8; nf++){
          sf[nf][0] = exp2f(fmaf(__int2float_rn(acc[nf][0]), dq, -mn0));
          sf[nf][1] = exp2f(fmaf(__int2float_rn(acc[nf][1]), dq, -mn0));
          sf[nf][2] = exp2f(fmaf(__int2float_rn(acc[nf][2]), dq, -mn1));
          sf[nf][3] = exp2f(fmaf(__int2float_rn(acc[nf][3]), dq, -mn1));
        }
      } else {
        #pragma unroll
        for (int nf = 0; nf < 8; nf++){
          sf[nf][0] = exp2f(sf[nf][0] - mn0);
          sf[nf][1] = exp2f(sf[nf][1] - mn0);
          sf[nf][2] = exp2f(sf[nf][2] - mn1);
          sf[nf][3] = exp2f(sf[nf][3] - mn1);
        }
      }
      // pairwise sum trees
      float t0A[4], t1A[4];
      #pragma unroll
      for (int p = 0; p < 4; p++){
        t0A[p] = (sf[2*p][0] + sf[2*p][1]) + (sf[2*p+1][0] + sf[2*p+1][1]);
        t1A[p] = (sf[2*p][2] + sf[2*p][3]) + (sf[2*p+1][2] + sf[2*p+1][3]);
      }
      float t0 = (t0A[0] + t0A[1]) + (t0A[2] + t0A[3]);
      float t1 = (t1A[0] + t1A[1]) + (t1A[2] + t1A[3]);
      l0 = l0*a0 + t0; l1 = l1*a1 + t1;
      m0 = mn0; m1 = mn1;
      if (__ballot_sync(0xffffffffu, raise)){
        #pragma unroll
        for (int n = 0; n < 16; n++){
          of[n][0]*=a0; of[n][1]*=a0; of[n][2]*=a1; of[n][3]*=a1;
        }
      }

      // --- pack P to f16 A-fragments ---
      uint32_t pfrag[4][4];
      #pragma unroll
      for (int kc = 0; kc < 4; kc++){
        __half2 p0 = __floats2half2_rn(sf[2*kc  ][0], sf[2*kc  ][1]);
        __half2 p1 = __floats2half2_rn(sf[2*kc  ][2], sf[2*kc  ][3]);
        __half2 p2 = __floats2half2_rn(sf[2*kc+1][0], sf[2*kc+1][1]);
        __half2 p3 = __floats2half2_rn(sf[2*kc+1][2], sf[2*kc+1][3]);
        pfrag[kc][0] = *(uint32_t*)&p0; pfrag[kc][1] = *(uint32_t*)&p1;
        pfrag[kc][2] = *(uint32_t*)&p2; pfrag[kc][3] = *(uint32_t*)&p3;
      }

      // --- O += P V : V^T fragments via ldmatrix.trans ---
      const uint32_t svb = smem_b + SV_OFF(st);
      #pragma unroll
      for (int jc = 0; jc < 4; jc++){
        #pragma unroll
        for (int dc = 0; dc < 8; dc++){
          uint32_t addr = svb + (jc*16 + jrow)*VPITCH + (dc*16 + dsel)*2;
          uint32_t v0, v1, v2, v3;
          ldmx4t(v0, v1, v2, v3, addr);
          mma16816(of[dc*2    ], pfrag[jc], v0, v1);
          mma16816(of[dc*2 + 1], pfrag[jc], v2, v3);
        }
      }
      __syncthreads();
    }

    // --- epilogue: reduce l over quad, normalize, f16-round, add v_mean ---
    l0 += __shfl_xor_sync(0xffffffffu, l0, 1);
    l0 += __shfl_xor_sync(0xffffffffu, l0, 2);
    l1 += __shfl_xor_sync(0xffffffffu, l1, 1);
    l1 += __shfl_xor_sync(0xffffffffu, l1, 2);
    float inv0 = 1.0f / l0, inv1 = 1.0f / l1;
    float* ob = out + ((size_t)b*SS)*HID + h*DD;
    const float* vm = g_vmean + bh*DD;
    #pragma unroll
    for (int n = 0; n < 16; n++){
      int d0 = n*8 + q2;
      float2 o0, o1;
      o0.x = __half2float(__float2half_rn(of[n][0]*inv0)) + vm[d0];
      o0.y = __half2float(__float2half_rn(of[n][1]*inv0)) + vm[d0+1];
      o1.x = __half2float(__float2half_rn(of[n][2]*inv1)) + vm[d0];
      o1.y = __half2float(__float2half_rn(of[n][3]*inv1)) + vm[d0+1];
      *(float2*)(ob + (size_t)i_r0*HID + d0) = o0;
      *(float2*)(ob + (size_t)i_r1*HID + d0) = o1;
    }

    // --- grab next work item ---
    if (tid == 0) s_next = atomicAdd(&g_wq, 1);
    __syncthreads();
    wi = s_next;
  }
}

// ---------------- launch ----------------
extern "C" void kernel_launch(void* const* d_in, const int* in_sizes, int n_in,
                              void* d_out, int out_size){
  const float* q = (const float*)d_in[0];
  const float* k = (const float*)d_in[1];
  const float* v = (const float*)d_in[2];
  const int* wl  = (const int*)d_in[3];
  const int* wr  = (const int*)d_in[4];
  float* out = (float*)d_out;

  cudaFuncSetAttribute(attn_kernel, cudaFuncAttributeMaxDynamicSharedMemorySize, SMEM_TOTAL);

  pre_k0<<<dim3(80, BB*HH), 256>>>(q, k, v);
  pre_k2<<<dim3(64, BB*HH), 256>>>(k, v);
  attn_kernel<<<ATTN_GRID, 128, SMEM_TOTAL>>>(wl, wr, out);
}

// round 10
// speedup vs baseline: 1.3161x; 1.0755x over previous
#include <cuda_runtime.h>
#include <cuda_fp16.h>
#include <math.h>
#include <stdint.h>

#define BB 2
#define SS 2048
#define HH 16
#define DD 128
#define HID (HH*DD)
#define SM_SCALE_L2E 0.12751649736230442f   /* (1/sqrt(128)) * log2(e) */
#define ATTN_GRID 592
#define N_ITEMS 1024

// ---------------- scratch (no allocation allowed) ----------------
__device__ signed char g_q8[(size_t)BB*HH*SS*DD];
__device__ signed char g_k8[(size_t)BB*HH*SS*DD];
__device__ __half      g_v16[(size_t)BB*HH*SS*DD];
__device__ float g_qscale[BB*HH*(SS/32)];
__device__ float g_kscale[BB*HH*(SS/64)];
__device__ float g_vmean[BB*HH*DD];
__device__ float g_kpart[BB*HH*32*DD];
__device__ float g_vpart[BB*HH*32*DD];
__device__ int   g_wq;

// ---------------- block absmax (256 threads / 8 warps) ----------------
__device__ __forceinline__ float block_absmax(float v, float* red){
  #pragma unroll
  for (int o = 16; o > 0; o >>= 1)
    v = fmaxf(v, __shfl_xor_sync(0xffffffffu, v, o));
  int w = threadIdx.x >> 5;
  if ((threadIdx.x & 31) == 0) red[w] = v;
  __syncthreads();
  float r = red[0];
  #pragma unroll
  for (int i = 1; i < 8; i++) r = fmaxf(r, red[i]);
  return r;
}

// ---------------- K0: mean partials (bx<16) + quant_q (bx>=16) ----------------
__global__ void __launch_bounds__(256)
pre_k0(const float* __restrict__ q, const float* __restrict__ k, const float* __restrict__ v){
  int bh = blockIdx.y, bx = blockIdx.x;
  int b = bh >> 4, h = bh & 15;
  int t = threadIdx.x;
  if (bx == 0 && bh == 0 && t == 0) g_wq = ATTN_GRID;   // reset work queue every replay
  if (bx < 16){
    int d = t & 127, hf = t >> 7;
    size_t base = ((size_t)b*SS + (size_t)bx*128 + (size_t)hf*64)*HID + h*DD + d;
    float ka0 = 0.f, va0 = 0.f, ka1 = 0.f, va1 = 0.f;
    #pragma unroll 8
    for (int r2 = 0; r2 < 64; r2 += 2){
      ka0 += k[base + (size_t)r2*HID];
      va0 += v[base + (size_t)r2*HID];
      ka1 += k[base + (size_t)(r2+1)*HID];
      va1 += v[base + (size_t)(r2+1)*HID];
    }
    g_kpart[((bh*16 + bx)*2 + hf)*DD + d] = ka0 + ka1;
    g_vpart[((bh*16 + bx)*2 + hf)*DD + d] = va0 + va1;
  } else {
    __shared__ float red[8];
    int g = bx - 16;                      // 32-row group
    size_t inbase = ((size_t)b*SS + (size_t)g*32)*HID + h*DD;
    float4 vals[4]; float amax = 0.f;
    #pragma unroll
    for (int i = 0; i < 4; i++){
      int f4 = t + i*256;
      int row = f4 >> 5, c4 = f4 & 31;
      float4 x = *(const float4*)(q + inbase + (size_t)row*HID + c4*4);
      vals[i] = x;
      amax = fmaxf(amax, fmaxf(fmaxf(fabsf(x.x), fabsf(x.y)), fmaxf(fabsf(x.z), fabsf(x.w))));
    }
    amax = block_absmax(amax, red);
    float scale = fmaxf(amax / 127.0f, 1e-8f);
    size_t obase = ((size_t)bh*SS + (size_t)g*32)*DD;
    #pragma unroll
    for (int i = 0; i < 4; i++){
      int f4 = t + i*256;
      int row = f4 >> 5, c4 = f4 & 31;
      char4 o;
      o.x = (signed char)(int)fminf(fmaxf(rintf(vals[i].x / scale), -127.f), 127.f);
      o.y = (signed char)(int)fminf(fmaxf(rintf(vals[i].y / scale), -127.f), 127.f);
      o.z = (signed char)(int)fminf(fmaxf(rintf(vals[i].z / scale), -127.f), 127.f);
      o.w = (signed char)(int)fminf(fmaxf(rintf(vals[i].w / scale), -127.f), 127.f);
      *(char4*)(g_q8 + obase + (size_t)row*DD + c4*4) = o;
    }
    if (t == 0) g_qscale[bh*64 + g] = scale;
  }
}

// ---------------- K1: quant_k (bx<32) + smooth_v (bx>=32); means in-block ----------------
__global__ void __launch_bounds__(256)
pre_k2(const float* __restrict__ k, const float* __restrict__ v){
  __shared__ float smean[128];
  int bh = blockIdx.y, bx = blockIdx.x;
  int b = bh >> 4, h = bh & 15;
  int t = threadIdx.x;
  if (t < 128){
    const float* part = (bx < 32) ? g_kpart : g_vpart;
    float a = 0.f;
    #pragma unroll
    for (int c = 0; c < 32; c++) a += part[(bh*32 + c)*DD + t];
    smean[t] = a / (float)SS;
    if (bx >= 32) g_vmean[bh*DD + t] = smean[t];
  }
  __syncthreads();
  if (bx < 32){
    __shared__ float red[8];
    int g = bx;
    size_t inbase = ((size_t)b*SS + (size_t)g*64)*HID + h*DD;
    float4 vals[8]; float amax = 0.f;
    #pragma unroll
    for (int i = 0; i < 8; i++){
      int f4 = t + i*256;
      int row = f4 >> 5, c4 = f4 & 31;
      float4 x = *(const float4*)(k + inbase + (size_t)row*HID + c4*4);
      x.x -= smean[c4*4]; x.y -= smean[c4*4+1]; x.z -= smean[c4*4+2]; x.w -= smean[c4*4+3];
      vals[i] = x;
      amax = fmaxf(amax, fmaxf(fmaxf(fabsf(x.x), fabsf(x.y)), fmaxf(fabsf(x.z), fabsf(x.w))));
    }
    amax = block_absmax(amax, red);
    float scale = fmaxf(amax / 127.0f, 1e-8f);
    size_t obase = ((size_t)bh*SS + (size_t)g*64)*DD;
    #pragma unroll
    for (int i = 0; i < 8; i++){
      int f4 = t + i*256;
      int row = f4 >> 5, c4 = f4 & 31;
      char4 o;
      o.x = (signed char)(int)fminf(fmaxf(rintf(vals[i].x / scale), -127.f), 127.f);
      o.y = (signed char)(int)fminf(fmaxf(rintf(vals[i].y / scale), -127.f), 127.f);
      o.z = (signed char)(int)fminf(fmaxf(rintf(vals[i].z / scale), -127.f), 127.f);
      o.w = (signed char)(int)fminf(fmaxf(rintf(vals[i].w / scale), -127.f), 127.f);
      *(char4*)(g_k8 + obase + (size_t)row*DD + c4*4) = o;
    }
    if (t == 0) g_kscale[bh*32 + g] = scale;
  } else {
    int g = bx - 32;
    size_t inbase = ((size_t)b*SS + (size_t)g*64)*HID + h*DD;
    size_t obase  = ((size_t)bh*SS + (size_t)g*64)*DD;
    #pragma unroll
    for (int i = 0; i < 8; i++){
      int f4 = t + i*256;
      int row = f4 >> 5, c4 = f4 & 31;
      float4 x = *(const float4*)(v + inbase + (size_t)row*HID + c4*4);
      __half2 h0 = __floats2half2_rn(x.x - smean[c4*4],   x.y - smean[c4*4+1]);
      __half2 h1 = __floats2half2_rn(x.z - smean[c4*4+2], x.w - smean[c4*4+3]);
      uint2 o; o.x = *(uint32_t*)&h0; o.y = *(uint32_t*)&h1;
      *(uint2*)(g_v16 + obase + (size_t)row*DD + c4*4) = o;
    }
  }
}

// ---------------- MMA helpers ----------------
__device__ __forceinline__ void mma16816(float c[4], const uint32_t a[4], uint32_t b0, uint32_t b1){
  asm volatile(
    "mma.sync.aligned.m16n8k16.row.col.f32.f16.f16.f32 "
    "{%0,%1,%2,%3}, {%4,%5,%6,%7}, {%8,%9}, {%0,%1,%2,%3};\n"
    : "+f"(c[0]), "+f"(c[1]), "+f"(c[2]), "+f"(c[3])
    : "r"(a[0]), "r"(a[1]), "r"(a[2]), "r"(a[3]), "r"(b0), "r"(b1));
}
__device__ __forceinline__ void mma_s8(int c[4], const uint32_t a[4], uint32_t b0, uint32_t b1){
  asm volatile(
    "mma.sync.aligned.m16n8k32.row.col.s32.s8.s8.s32 "
    "{%0,%1,%2,%3}, {%4,%5,%6,%7}, {%8,%9}, {%0,%1,%2,%3};\n"
    : "+r"(c[0]), "+r"(c[1]), "+r"(c[2]), "+r"(c[3])
    : "r"(a[0]), "r"(a[1]), "r"(a[2]), "r"(a[3]), "r"(b0), "r"(b1));
}
__device__ __forceinline__ void ldmx4(uint32_t& t0, uint32_t& t1, uint32_t& t2, uint32_t& t3, uint32_t addr){
  asm volatile("ldmatrix.sync.aligned.m8n8.x4.shared.b16 {%0,%1,%2,%3}, [%4];\n"
    : "=r"(t0), "=r"(t1), "=r"(t2), "=r"(t3) : "r"(addr));
}
__device__ __forceinline__ void ldmx4t(uint32_t& t0, uint32_t& t1, uint32_t& t2, uint32_t& t3, uint32_t addr){
  asm volatile("ldmatrix.sync.aligned.m8n8.x4.trans.shared.b16 {%0,%1,%2,%3}, [%4];\n"
    : "=r"(t0), "=r"(t1), "=r"(t2), "=r"(t3) : "r"(addr));
}
#define CP16(dst, src) asm volatile("cp.async.cg.shared.global [%0], [%1], 16;\n" :: "r"(dst), "l"(src) : "memory")

#define KPITCH 144
#define VPITCH 272
#define SK_OFF(st) ((st)*64*KPITCH)
#define SV_OFF(st) (2*64*KPITCH + (st)*64*VPITCH)
#define SMEM_TOTAL (2*64*KPITCH + 2*64*VPITCH)   // 53248

// ---------------- main attention kernel (persistent, 4 CTA/SM, streamed softmax/PV) ----------------
__global__ void __launch_bounds__(128, 4)
attn_kernel(const int* __restrict__ wlp, const int* __restrict__ wrp, float* __restrict__ out){
  extern __shared__ char smem[];
  __shared__ int s_next;
  const uint32_t smem_b = (uint32_t)__cvta_generic_to_shared(smem);

  const int tid = threadIdx.x, wid = tid >> 5, lane = tid & 31;
  const int r   = lane >> 2, q2 = (lane & 3) * 2, c4 = (lane & 3) * 4;
  const int wl = *wlp, wr = *wrp;
  const int ldm_g = lane >> 3;
  const uint32_t kfrag_off = (uint32_t)(((ldm_g >> 1)*8 + (lane & 7))*KPITCH + (ldm_g & 1)*16);
  const int jrow = lane & 15;
  const int dsel = (lane & 16) ? 8 : 0;
  const int qrow = wid*16 + r;

  int wi = blockIdx.x;
  while (wi < N_ITEMS){
    const int q_ord = wi >> 5;
    const int bh = wi & 31;
    const int xq = (q_ord & 1) ? (16 + (q_ord >> 1)) : (15 - (q_ord >> 1));
    const int i0 = xq * 64;
    const int b = bh >> 4, h = bh & 15;

    const signed char* Qg = g_q8 + ((size_t)bh*SS + i0)*DD;
    const signed char* Kg = g_k8 + (size_t)bh*SS*DD;
    const __half*      Vg = g_v16 + (size_t)bh*SS*DD;

    // --- stage Q into stage-0 K region, build int8 A-fragments ---
    {
      char* sQ = smem;
      #pragma unroll
      for (int it = tid; it < 512; it += 128){
        int row = it >> 3, seg = it & 7;
        *(uint4*)(sQ + row*KPITCH + seg*16) = *(const uint4*)(Qg + row*128 + seg*16);
      }
    }
    __syncthreads();
    uint32_t afrag[4][4];
    #pragma unroll
    for (int kc = 0; kc < 4; kc++){
      const char* sQ = smem;
      afrag[kc][0] = *(const uint32_t*)(sQ + (qrow  )*KPITCH + kc*32 + c4     );
      afrag[kc][1] = *(const uint32_t*)(sQ + (qrow+8)*KPITCH + kc*32 + c4     );
      afrag[kc][2] = *(const uint32_t*)(sQ + (qrow  )*KPITCH + kc*32 + c4 + 16);
      afrag[kc][3] = *(const uint32_t*)(sQ + (qrow+8)*KPITCH + kc*32 + c4 + 16);
    }
    __syncthreads();

    const float qsl = g_qscale[bh*(SS/32) + ((i0 + wid*16) >> 5)] * SM_SCALE_L2E;
    const int i_r0 = i0 + qrow, i_r1 = i_r0 + 8;
    const int lo0 = (wl < 0) ? -0x40000000 : i_r0 - wl;
    const int hi0 = (wr < 0) ?  0x40000000 : i_r0 + wr;
    const int lo1 = (wl < 0) ? -0x40000000 : i_r1 - wl;
    const int hi1 = (wr < 0) ?  0x40000000 : i_r1 + wr;

    float of[16][4];
    #pragma unroll
    for (int n = 0; n < 16; n++){ of[n][0]=0.f; of[n][1]=0.f; of[n][2]=0.f; of[n][3]=0.f; }
    float m0 = -1e30f, m1 = -1e30f, l0 = 0.f, l1 = 0.f;

    int jlo = (wl >= 0) ? max(0, i0 - wl) : 0;
    int jhi = (wr >= 0) ? min(SS-1, i0 + 63 + wr) : SS-1;
    const int jloT = jlo & ~63;
    const int nt = ((jhi - jloT) >> 6) + 1;

    auto issue = [&](int st, int j0){
      uint32_t kb = smem_b + SK_OFF(st);
      const signed char* kg = Kg + (size_t)j0*128;
      #pragma unroll
      for (int c = tid; c < 512; c += 128){
        int row = c >> 3, seg = c & 7;
        CP16(kb + row*KPITCH + seg*16, kg + row*128 + seg*16);
      }
      uint32_t vb = smem_b + SV_OFF(st);
      const __half* vg = Vg + (size_t)j0*128;
      #pragma unroll
      for (int c = tid; c < 1024; c += 128){
        int row = c >> 4, seg = c & 15;
        CP16(vb + row*VPITCH + seg*16, (const char*)vg + row*256 + seg*16);
      }
      asm volatile("cp.async.commit_group;\n" ::: "memory");
    };

    issue(0, jloT);
    float ksc = g_kscale[bh*(SS/64) + (jloT >> 6)];

    for (int it = 0; it < nt; it++){
      const int j0 = jloT + it*64;
      const int st = it & 1;
      if (it + 1 < nt){
        issue(st ^ 1, j0 + 64);
        asm volatile("cp.async.wait_group 1;\n" ::: "memory");
      } else {
        asm volatile("cp.async.wait_group 0;\n" ::: "memory");
      }
      __syncthreads();

      const float dq = qsl * ksc;
      if (it + 1 < nt) ksc = g_kscale[bh*(SS/64) + ((j0 + 64) >> 6)];

      // --- S = Q K^T (int8 MMA, exact); B-frags via ldmatrix.x4 ---
      int acc[8][4];
      #pragma unroll
      for (int n = 0; n < 8; n++){ acc[n][0]=0; acc[n][1]=0; acc[n][2]=0; acc[n][3]=0; }
      const uint32_t kfb = smem_b + SK_OFF(st) + kfrag_off;
      #pragma unroll
      for (int m = 0; m < 16; m++){
        const int kc = m >> 2, nfp = m & 3;
        uint32_t b0, b1, b2, b3;
        ldmx4(b0, b1, b2, b3, kfb + nfp*(16*KPITCH) + kc*32);
        mma_s8(acc[nfp*2    ], afrag[kc], b0, b1);
        mma_s8(acc[nfp*2 + 1], afrag[kc], b2, b3);
      }

      const bool full = ((wl < 0) || (j0 >= i0 + 63 - wl)) && ((wr < 0) || (j0 + 63 <= i0 + wr));

      // --- pass 1: row max (int domain on full tiles) ---
      float mt0, mt1;
      if (full){
        int iA0[4], iA1[4];
        #pragma unroll
        for (int p = 0; p < 4; p++){
          iA0[p] = max(max(acc[2*p][0], acc[2*p][1]), max(acc[2*p+1][0], acc[2*p+1][1]));
          iA1[p] = max(max(acc[2*p][2], acc[2*p][3]), max(acc[2*p+1][2], acc[2*p+1][3]));
        }
        mt0 = __int2float_rn(max(max(iA0[0], iA0[1]), max(iA0[2], iA0[3]))) * dq;
        mt1 = __int2float_rn(max(max(iA1[0], iA1[1]), max(iA1[2], iA1[3]))) * dq;
      } else {
        mt0 = -INFINITY; mt1 = -INFINITY;
        #pragma unroll
        for (int nf = 0; nf < 8; nf++){
          int jc = j0 + nf*8 + q2;
          float s00 = (jc   >= lo0 && jc   <= hi0) ? __int2float_rn(acc[nf][0]) * dq : -INFINITY;
          float s01 = (jc+1 >= lo0 && jc+1 <= hi0) ? __int2float_rn(acc[nf][1]) * dq : -INFINITY;
          float s10 = (jc   >= lo1 && jc   <= hi1) ? __int2float_rn(acc[nf][2]) * dq : -INFINITY;
          float s11 = (jc+1 >= lo1 && jc+1 <= hi1) ? __int2float_rn(acc[nf][3]) * dq : -INFINITY;
          mt0 = fmaxf(mt0, fmaxf(s00, s01));
          mt1 = fmaxf(mt1, fmaxf(s10, s11));
        }
      }
      mt0 = fmaxf(mt0, __shfl_xor_sync(0xffffffffu, mt0, 1));
      mt0 = fmaxf(mt0, __shfl_xor_sync(0xffffffffu, mt0, 2));
      mt1 = fmaxf(mt1, __shfl_xor_sync(0xffffffffu, mt1, 1));
      mt1 = fmaxf(mt1, __shfl_xor_sync(0xffffffffu, mt1, 2));

      const bool raise = (mt0 > m0) || (mt1 > m1);
      const float mn0 = fmaxf(m0, mt0), mn1 = fmaxf(m1, mt1);
      const float a0 = exp2f(m0 - mn0), a1 = exp2f(m1 - mn1);
      if (__ballot_sync(0xffffffffu, raise)){
        #pragma unroll
        for (int n = 0; n < 16; n++){
          of[n][0]*=a0; of[n][1]*=a0; of[n][2]*=a1; of[n][3]*=a1;
        }
      }

      // --- pass 2 (streamed): per kc-chunk exp+pack then PV ---
      const uint32_t svb = smem_b + SV_OFF(st);
      float t0 = 0.f, t1 = 0.f;
      #pragma unroll
      for (int kc = 0; kc < 4; kc++){
        float e0[4], e1[4];
        if (full){
          #pragma unroll
          for (int hnf = 0; hnf < 2; hnf++){
            const int nf = 2*kc + hnf;
            e0[2*hnf  ] = exp2f(fmaf(__int2float_rn(acc[nf][0]), dq, -mn0));
            e0[2*hnf+1] = exp2f(fmaf(__int2float_rn(acc[nf][1]), dq, -mn0));
            e1[2*hnf  ] = exp2f(fmaf(__int2float_rn(acc[nf][2]), dq, -mn1));
            e1[2*hnf+1] = exp2f(fmaf(__int2float_rn(acc[nf][3]), dq, -mn1));
          }
        } else {
          #pragma unroll
          for (int hnf = 0; hnf < 2; hnf++){
            const int nf = 2*kc + hnf;
            int jc = j0 + nf*8 + q2;
            float s00 = (jc   >= lo0 && jc   <= hi0) ? __int2float_rn(acc[nf][0]) * dq : -INFINITY;
            float s01 = (jc+1 >= lo0 && jc+1 <= hi0) ? __int2float_rn(acc[nf][1]) * dq : -INFINITY;
            float s10 = (jc   >= lo1 && jc   <= hi1) ? __int2float_rn(acc[nf][2]) * dq : -INFINITY;
            float s11 = (jc+1 >= lo1 && jc+1 <= hi1) ? __int2float_rn(acc[nf][3]) * dq : -INFINITY;
            e0[2*hnf  ] = exp2f(s00 - mn0);
            e0[2*hnf+1] = exp2f(s01 - mn0);
            e1[2*hnf  ] = exp2f(s10 - mn1);
            e1[2*hnf+1] = exp2f(s11 - mn1);
          }
        }
        t0 += (e0[0] + e0[1]) + (e0[2] + e0[3]);
        t1 += (e1[0] + e1[1]) + (e1[2] + e1[3]);
        uint32_t pfrag[4];
        {
          __half2 p0 = __floats2half2_rn(e0[0], e0[1]);
          __half2 p1 = __floats2half2_rn(e1[0], e1[1]);
          __half2 p2 = __floats2half2_rn(e0[2], e0[3]);
          __half2 p3 = __floats2half2_rn(e1[2], e1[3]);
          pfrag[0] = *(uint32_t*)&p0; pfrag[1] = *(uint32_t*)&p1;
          pfrag[2] = *(uint32_t*)&p2; pfrag[3] = *(uint32_t*)&p3;
        }
        // PV for this key-chunk (jc == kc)
        #pragma unroll
        for (int dc = 0; dc < 8; dc++){
          uint32_t addr = svb + (kc*16 + jrow)*VPITCH + (dc*16 + dsel)*2;
          uint32_t v0, v1, v2, v3;
          ldmx4t(v0, v1, v2, v3, addr);
          mma16816(of[dc*2    ], pfrag, v0, v1);
          mma16816(of[dc*2 + 1], pfrag, v2, v3);
        }
      }
      l0 = l0*a0 + t0; l1 = l1*a1 + t1;
      m0 = mn0; m1 = mn1;
      __syncthreads();
    }

    // --- epilogue: reduce l over quad, normalize, f16-round, add v_mean ---
    l0 += __shfl_xor_sync(0xffffffffu, l0, 1);
    l0 += __shfl_xor_sync(0xffffffffu, l0, 2);
    l1 += __shfl_xor_sync(0xffffffffu, l1, 1);
    l1 += __shfl_xor_sync(0xffffffffu, l1, 2);
    float inv0 = 1.0f / l0, inv1 = 1.0f / l1;
    float* ob = out + ((size_t)b*SS)*HID + h*DD;
    const float* vm = g_vmean + bh*DD;
    #pragma unroll
    for (int n = 0; n < 16; n++){
      int d0 = n*8 + q2;
      float2 o0, o1;
      o0.x = __half2float(__float2half_rn(of[n][0]*inv0)) + vm[d0];
      o0.y = __half2float(__float2half_rn(of[n][1]*inv0)) + vm[d0+1];
      o1.x = __half2float(__float2half_rn(of[n][2]*inv1)) + vm[d0];
      o1.y = __half2float(__float2half_rn(of[n][3]*inv1)) + vm[d0+1];
      *(float2*)(ob + (size_t)i_r0*HID + d0) = o0;
      *(float2*)(ob + (size_t)i_r1*HID + d0) = o1;
    }

    // --- grab next work item ---
    if (tid == 0) s_next = atomicAdd(&g_wq, 1);
    __syncthreads();
    wi = s_next;
  }
}

// ---------------- launch ----------------
extern "C" void kernel_launch(void* const* d_in, const int* in_sizes, int n_in,
                              void* d_out, int out_size){
  const float* q = (const float*)d_in[0];
  const float* k = (const float*)d_in[1];
  const float* v = (const float*)d_in[2];
  const int* wl  = (const int*)d_in[3];
  const int* wr  = (const int*)d_in[4];
  float* out = (float*)d_out;

  cudaFuncSetAttribute(attn_kernel, cudaFuncAttributeMaxDynamicSharedMemorySize, SMEM_TOTAL);

  pre_k0<<<dim3(80, BB*HH), 256>>>(q, k, v);
  pre_k2<<<dim3(64, BB*HH), 256>>>(k, v);
  attn_kernel<<<ATTN_GRID, 128, SMEM_TOTAL>>>(wl, wr, out);
}

// round 11
// speedup vs baseline: 1.3184x; 1.0018x over previous
#include <cuda_runtime.h>
#include <cuda_fp16.h>
#include <math.h>
#include <stdint.h>

#define BB 2
#define SS 2048
#define HH 16
#define DD 128
#define HID (HH*DD)
#define SM_SCALE_L2E 0.12751649736230442f   /* (1/sqrt(128)) * log2(e) */
#define ATTN_GRID 592
#define N_ITEMS 1024

// ---------------- scratch (no allocation allowed) ----------------
__device__ signed char g_k8[(size_t)BB*HH*SS*DD];
__device__ __half      g_v16[(size_t)BB*HH*SS*DD];
__device__ float g_kscale[BB*HH*(SS/64)];
__device__ float g_vmean[BB*HH*DD];
__device__ float g_kpart[BB*HH*32*DD];
__device__ float g_vpart[BB*HH*32*DD];
__device__ int   g_wq;

// ---------------- block absmax (256 threads / 8 warps) ----------------
__device__ __forceinline__ float block_absmax(float v, float* red){
  #pragma unroll
  for (int o = 16; o > 0; o >>= 1)
    v = fmaxf(v, __shfl_xor_sync(0xffffffffu, v, o));
  int w = threadIdx.x >> 5;
  if ((threadIdx.x & 31) == 0) red[w] = v;
  __syncthreads();
  float r = red[0];
  #pragma unroll
  for (int i = 1; i < 8; i++) r = fmaxf(r, red[i]);
  return r;
}

// ---------------- K0: k/v mean partials only ----------------
__global__ void __launch_bounds__(256)
pre_k0(const float* __restrict__ k, const float* __restrict__ v){
  int bh = blockIdx.y, bx = blockIdx.x;
  int b = bh >> 4, h = bh & 15;
  int t = threadIdx.x;
  if (bx == 0 && bh == 0 && t == 0) g_wq = ATTN_GRID;   // reset work queue every replay
  int d = t & 127, hf = t >> 7;
  size_t base = ((size_t)b*SS + (size_t)bx*128 + (size_t)hf*64)*HID + h*DD + d;
  float ka0 = 0.f, va0 = 0.f, ka1 = 0.f, va1 = 0.f;
  #pragma unroll 8
  for (int r2 = 0; r2 < 64; r2 += 2){
    ka0 += k[base + (size_t)r2*HID];
    va0 += v[base + (size_t)r2*HID];
    ka1 += k[base + (size_t)(r2+1)*HID];
    va1 += v[base + (size_t)(r2+1)*HID];
  }
  g_kpart[((bh*16 + bx)*2 + hf)*DD + d] = ka0 + ka1;
  g_vpart[((bh*16 + bx)*2 + hf)*DD + d] = va0 + va1;
}

// ---------------- K1: quant_k (bx<32) + smooth_v (bx>=32); means in-block ----------------
__global__ void __launch_bounds__(256)
pre_k2(const float* __restrict__ k, const float* __restrict__ v){
  __shared__ float smean[128];
  int bh = blockIdx.y, bx = blockIdx.x;
  int b = bh >> 4, h = bh & 15;
  int t = threadIdx.x;
  if (t < 128){
    const float* part = (bx < 32) ? g_kpart : g_vpart;
    float a = 0.f;
    #pragma unroll
    for (int c = 0; c < 32; c++) a += part[(bh*32 + c)*DD + t];
    smean[t] = a / (float)SS;
    if (bx >= 32) g_vmean[bh*DD + t] = smean[t];
  }
  __syncthreads();
  if (bx < 32){
    __shared__ float red[8];
    int g = bx;
    size_t inbase = ((size_t)b*SS + (size_t)g*64)*HID + h*DD;
    float4 vals[8]; float amax = 0.f;
    #pragma unroll
    for (int i = 0; i < 8; i++){
      int f4 = t + i*256;
      int row = f4 >> 5, c4 = f4 & 31;
      float4 x = *(const float4*)(k + inbase + (size_t)row*HID + c4*4);
      x.x -= smean[c4*4]; x.y -= smean[c4*4+1]; x.z -= smean[c4*4+2]; x.w -= smean[c4*4+3];
      vals[i] = x;
      amax = fmaxf(amax, fmaxf(fmaxf(fabsf(x.x), fabsf(x.y)), fmaxf(fabsf(x.z), fabsf(x.w))));
    }
    amax = block_absmax(amax, red);
    float scale = fmaxf(amax / 127.0f, 1e-8f);
    size_t obase = ((size_t)bh*SS + (size_t)g*64)*DD;
    #pragma unroll
    for (int i = 0; i < 8; i++){
      int f4 = t + i*256;
      int row = f4 >> 5, c4 = f4 & 31;
      char4 o;
      o.x = (signed char)(int)fminf(fmaxf(rintf(vals[i].x / scale), -127.f), 127.f);
      o.y = (signed char)(int)fminf(fmaxf(rintf(vals[i].y / scale), -127.f), 127.f);
      o.z = (signed char)(int)fminf(fmaxf(rintf(vals[i].z / scale), -127.f), 127.f);
      o.w = (signed char)(int)fminf(fmaxf(rintf(vals[i].w / scale), -127.f), 127.f);
      *(char4*)(g_k8 + obase + (size_t)row*DD + c4*4) = o;
    }
    if (t == 0) g_kscale[bh*32 + g] = scale;
  } else {
    int g = bx - 32;
    size_t inbase = ((size_t)b*SS + (size_t)g*64)*HID + h*DD;
    size_t obase  = ((size_t)bh*SS + (size_t)g*64)*DD;
    #pragma unroll
    for (int i = 0; i < 8; i++){
      int f4 = t + i*256;
      int row = f4 >> 5, c4 = f4 & 31;
      float4 x = *(const float4*)(v + inbase + (size_t)row*HID + c4*4);
      __half2 h0 = __floats2half2_rn(x.x - smean[c4*4],   x.y - smean[c4*4+1]);
      __half2 h1 = __floats2half2_rn(x.z - smean[c4*4+2], x.w - smean[c4*4+3]);
      uint2 o; o.x = *(uint32_t*)&h0; o.y = *(uint32_t*)&h1;
      *(uint2*)(g_v16 + obase + (size_t)row*DD + c4*4) = o;
    }
  }
}

// ---------------- MMA helpers ----------------
__device__ __forceinline__ void mma16816(float c[4], const uint32_t a[4], uint32_t b0, uint32_t b1){
  asm volatile(
    "mma.sync.aligned.m16n8k16.row.col.f32.f16.f16.f32 "
    "{%0,%1,%2,%3}, {%4,%5,%6,%7}, {%8,%9}, {%0,%1,%2,%3};\n"
    : "+f"(c[0]), "+f"(c[1]), "+f"(c[2]), "+f"(c[3])
    : "r"(a[0]), "r"(a[1]), "r"(a[2]), "r"(a[3]), "r"(b0), "r"(b1));
}
__device__ __forceinline__ void mma_s8(int c[4], const uint32_t a[4], uint32_t b0, uint32_t b1){
  asm volatile(
    "mma.sync.aligned.m16n8k32.row.col.s32.s8.s8.s32 "
    "{%0,%1,%2,%3}, {%4,%5,%6,%7}, {%8,%9}, {%0,%1,%2,%3};\n"
    : "+r"(c[0]), "+r"(c[1]), "+r"(c[2]), "+r"(c[3])
    : "r"(a[0]), "r"(a[1]), "r"(a[2]), "r"(a[3]), "r"(b0), "r"(b1));
}
__device__ __forceinline__ void ldmx4(uint32_t& t0, uint32_t& t1, uint32_t& t2, uint32_t& t3, uint32_t addr){
  asm volatile("ldmatrix.sync.aligned.m8n8.x4.shared.b16 {%0,%1,%2,%3}, [%4];\n"
    : "=r"(t0), "=r"(t1), "=r"(t2), "=r"(t3) : "r"(addr));
}
__device__ __forceinline__ void ldmx4t(uint32_t& t0, uint32_t& t1, uint32_t& t2, uint32_t& t3, uint32_t addr){
  asm volatile("ldmatrix.sync.aligned.m8n8.x4.trans.shared.b16 {%0,%1,%2,%3}, [%4];\n"
    : "=r"(t0), "=r"(t1), "=r"(t2), "=r"(t3) : "r"(addr));
}
#define CP16(dst, src) asm volatile("cp.async.cg.shared.global [%0], [%1], 16;\n" :: "r"(dst), "l"(src) : "memory")

#define KPITCH 144
#define VPITCH 272
#define SK_OFF(st) ((st)*64*KPITCH)
#define SV_OFF(st) (2*64*KPITCH + (st)*64*VPITCH)
#define SMEM_TOTAL (2*64*KPITCH + 2*64*VPITCH)   // 53248

// ---------------- main attention kernel (persistent, 4 CTA/SM, fused Q-quant) ----------------
__global__ void __launch_bounds__(128, 4)
attn_kernel(const float* __restrict__ qsrc,
            const int* __restrict__ wlp, const int* __restrict__ wrp,
            float* __restrict__ out){
  extern __shared__ char smem[];
  __shared__ int s_next;
  __shared__ float qred[4];
  const uint32_t smem_b = (uint32_t)__cvta_generic_to_shared(smem);

  const int tid = threadIdx.x, wid = tid >> 5, lane = tid & 31;
  const int r   = lane >> 2, q2 = (lane & 3) * 2, c4 = (lane & 3) * 4;
  const int wl = *wlp, wr = *wrp;
  const int ldm_g = lane >> 3;
  const uint32_t kfrag_off = (uint32_t)(((ldm_g >> 1)*8 + (lane & 7))*KPITCH + (ldm_g & 1)*16);
  const int jrow = lane & 15;
  const int dsel = (lane & 16) ? 8 : 0;
  const int qrow = wid*16 + r;

  int wi = blockIdx.x;
  while (wi < N_ITEMS){
    const int q_ord = wi >> 5;
    const int bh = wi & 31;
    const int xq = (q_ord & 1) ? (16 + (q_ord >> 1)) : (15 - (q_ord >> 1));
    const int i0 = xq * 64;
    const int b = bh >> 4, h = bh & 15;

    const signed char* Kg = g_k8 + (size_t)bh*SS*DD;
    const __half*      Vg = g_v16 + (size_t)bh*SS*DD;

    int jlo = (wl >= 0) ? max(0, i0 - wl) : 0;
    int jhi = (wr >= 0) ? min(SS-1, i0 + 63 + wr) : SS-1;
    const int jloT = jlo & ~63;
    const int nt = ((jhi - jloT) >> 6) + 1;

    auto issue = [&](int st, int j0){
      uint32_t kb = smem_b + SK_OFF(st);
      const signed char* kg = Kg + (size_t)j0*128;
      #pragma unroll
      for (int c = tid; c < 512; c += 128){
        int row = c >> 3, seg = c & 7;
        CP16(kb + row*KPITCH + seg*16, kg + row*128 + seg*16);
      }
      uint32_t vb = smem_b + SV_OFF(st);
      const __half* vg = Vg + (size_t)j0*128;
      #pragma unroll
      for (int c = tid; c < 1024; c += 128){
        int row = c >> 4, seg = c & 15;
        CP16(vb + row*VPITCH + seg*16, (const char*)vg + row*256 + seg*16);
      }
      asm volatile("cp.async.commit_group;\n" ::: "memory");
    };

    issue(0, jloT);   // tile-0 load overlaps Q quantization below

    // ---- fused Q quantization: f32 gmem -> int8 afrag (bit-identical to ref) ----
    const float* row0 = qsrc + ((size_t)b*SS + i0 + qrow)*HID + h*DD;
    const float* row1 = row0 + (size_t)8*HID;
    float amax = 0.f;
    #pragma unroll
    for (int kc = 0; kc < 4; kc++){
      #pragma unroll
      for (int j = 0; j < 4; j++){
        const float* rp = (j & 1) ? row1 : row0;
        int col = kc*32 + c4 + ((j & 2) ? 16 : 0);
        float4 x = *(const float4*)(rp + col);
        amax = fmaxf(amax, fmaxf(fmaxf(fabsf(x.x), fabsf(x.y)), fmaxf(fabsf(x.z), fabsf(x.w))));
      }
    }
    #pragma unroll
    for (int o = 16; o > 0; o >>= 1)
      amax = fmaxf(amax, __shfl_xor_sync(0xffffffffu, amax, o));
    if (lane == 0) qred[wid] = amax;
    __syncthreads();
    const float qscale = fmaxf(fmaxf(qred[wid], qred[wid ^ 1]) / 127.0f, 1e-8f);
    uint32_t afrag[4][4];
    #pragma unroll
    for (int kc = 0; kc < 4; kc++){
      #pragma unroll
      for (int j = 0; j < 4; j++){
        const float* rp = (j & 1) ? row1 : row0;
        int col = kc*32 + c4 + ((j & 2) ? 16 : 0);
        float4 x = *(const float4*)(rp + col);   // L1-resident reload
        int b0 = (int)fminf(fmaxf(rintf(x.x / qscale), -127.f), 127.f);
        int b1 = (int)fminf(fmaxf(rintf(x.y / qscale), -127.f), 127.f);
        int b2 = (int)fminf(fmaxf(rintf(x.z / qscale), -127.f), 127.f);
        int b3 = (int)fminf(fmaxf(rintf(x.w / qscale), -127.f), 127.f);
        afrag[kc][j] = (uint32_t)(b0 & 0xff) | ((uint32_t)(b1 & 0xff) << 8)
                     | ((uint32_t)(b2 & 0xff) << 16) | ((uint32_t)(b3 & 0xff) << 24);
      }
    }

    const float qsl = qscale * SM_SCALE_L2E;
    const int i_r0 = i0 + qrow, i_r1 = i_r0 + 8;
    const int lo0 = (wl < 0) ? -0x40000000 : i_r0 - wl;
    const int hi0 = (wr < 0) ?  0x40000000 : i_r0 + wr;
    const int lo1 = (wl < 0) ? -0x40000000 : i_r1 - wl;
    const int hi1 = (wr < 0) ?  0x40000000 : i_r1 + wr;

    float of[16][4];
    #pragma unroll
    for (int n = 0; n < 16; n++){ of[n][0]=0.f; of[n][1]=0.f; of[n][2]=0.f; of[n][3]=0.f; }
    float m0 = -1e30f, m1 = -1e30f, l0 = 0.f, l1 = 0.f;

    float ksc = g_kscale[bh*(SS/64) + (jloT >> 6)];

    for (int it = 0; it < nt; it++){
      const int j0 = jloT + it*64;
      const int st = it & 1;
      if (it + 1 < nt){
        issue(st ^ 1, j0 + 64);
        asm volatile("cp.async.wait_group 1;\n" ::: "memory");
      } else {
        asm volatile("cp.async.wait_group 0;\n" ::: "memory");
      }
      __syncthreads();

      const float dq = qsl * ksc;
      if (it + 1 < nt) ksc = g_kscale[bh*(SS/64) + ((j0 + 64) >> 6)];

      // --- S = Q K^T (int8 MMA, exact); B-frags via ldmatrix.x4 ---
      int acc[8][4];
      #pragma unroll
      for (int n = 0; n < 8; n++){ acc[n][0]=0; acc[n][1]=0; acc[n][2]=0; acc[n][3]=0; }
      const uint32_t kfb = smem_b + SK_OFF(st) + kfrag_off;
      #pragma unroll
      for (int m = 0; m < 16; m++){
        const int kc = m >> 2, nfp = m & 3;
        uint32_t b0, b1, b2, b3;
        ldmx4(b0, b1, b2, b3, kfb + nfp*(16*KPITCH) + kc*32);
        mma_s8(acc[nfp*2    ], afrag[kc], b0, b1);
        mma_s8(acc[nfp*2 + 1], afrag[kc], b2, b3);
      }

      const bool full = ((wl < 0) || (j0 >= i0 + 63 - wl)) && ((wr < 0) || (j0 + 63 <= i0 + wr));

      // --- pass 1: row max (int domain on full tiles) ---
      float mt0, mt1;
      if (full){
        int iA0[4], iA1[4];
        #pragma unroll
        for (int p = 0; p < 4; p++){
          iA0[p] = max(max(acc[2*p][0], acc[2*p][1]), max(acc[2*p+1][0], acc[2*p+1][1]));
          iA1[p] = max(max(acc[2*p][2], acc[2*p][3]), max(acc[2*p+1][2], acc[2*p+1][3]));
        }
        mt0 = __int2float_rn(max(max(iA0[0], iA0[1]), max(iA0[2], iA0[3]))) * dq;
        mt1 = __int2float_rn(max(max(iA1[0], iA1[1]), max(iA1[2], iA1[3]))) * dq;
      } else {
        mt0 = -INFINITY; mt1 = -INFINITY;
        #pragma unroll
        for (int nf = 0; nf < 8; nf++){
          int jc = j0 + nf*8 + q2;
          float s00 = (jc   >= lo0 && jc   <= hi0) ? __int2float_rn(acc[nf][0]) * dq : -INFINITY;
          float s01 = (jc+1 >= lo0 && jc+1 <= hi0) ? __int2float_rn(acc[nf][1]) * dq : -INFINITY;
          float s10 = (jc   >= lo1 && jc   <= hi1) ? __int2float_rn(acc[nf][2]) * dq : -INFINITY;
          float s11 = (jc+1 >= lo1 && jc+1 <= hi1) ? __int2float_rn(acc[nf][3]) * dq : -INFINITY;
          mt0 = fmaxf(mt0, fmaxf(s00, s01));
          mt1 = fmaxf(mt1, fmaxf(s10, s11));
        }
      }
      mt0 = fmaxf(mt0, __shfl_xor_sync(0xffffffffu, mt0, 1));
      mt0 = fmaxf(mt0, __shfl_xor_sync(0xffffffffu, mt0, 2));
      mt1 = fmaxf(mt1, __shfl_xor_sync(0xffffffffu, mt1, 1));
      mt1 = fmaxf(mt1, __shfl_xor_sync(0xffffffffu, mt1, 2));

      const bool raise = (mt0 > m0) || (mt1 > m1);
      const float mn0 = fmaxf(m0, mt0), mn1 = fmaxf(m1, mt1);
      const float a0 = exp2f(m0 - mn0), a1 = exp2f(m1 - mn1);
      if (__ballot_sync(0xffffffffu, raise)){
        #pragma unroll
        for (int n = 0; n < 16; n++){
          of[n][0]*=a0; of[n][1]*=a0; of[n][2]*=a1; of[n][3]*=a1;
        }
      }

      // --- pass 2 (streamed): per kc-chunk exp+pack then PV ---
      const uint32_t svb = smem_b + SV_OFF(st);
      float t0 = 0.f, t1 = 0.f;
      #pragma unroll
      for (int kc = 0; kc < 4; kc++){
        float e0[4], e1[4];
        if (full){
          #pragma unroll
          for (int hnf = 0; hnf < 2; hnf++){
            const int nf = 2*kc + hnf;
            e0[2*hnf  ] = exp2f(fmaf(__int2float_rn(acc[nf][0]), dq, -mn0));
            e0[2*hnf+1] = exp2f(fmaf(__int2float_rn(acc[nf][1]), dq, -mn0));
            e1[2*hnf  ] = exp2f(fmaf(__int2float_rn(acc[nf][2]), dq, -mn1));
            e1[2*hnf+1] = exp2f(fmaf(__int2float_rn(acc[nf][3]), dq, -mn1));
          }
        } else {
          #pragma unroll
          for (int hnf = 0; hnf < 2; hnf++){
            const int nf = 2*kc + hnf;
            int jc = j0 + nf*8 + q2;
            float s00 = (jc   >= lo0 && jc   <= hi0) ? __int2float_rn(acc[nf][0]) * dq : -INFINITY;
            float s01 = (jc+1 >= lo0 && jc+1 <= hi0) ? __int2float_rn(acc[nf][1]) * dq : -INFINITY;
            float s10 = (jc   >= lo1 && jc   <= hi1) ? __int2float_rn(acc[nf][2]) * dq : -INFINITY;
            float s11 = (jc+1 >= lo1 && jc+1 <= hi1) ? __int2float_rn(acc[nf][3]) * dq : -INFINITY;
            e0[2*hnf  ] = exp2f(s00 - mn0);
            e0[2*hnf+1] = exp2f(s01 - mn0);
            e1[2*hnf  ] = exp2f(s10 - mn1);
            e1[2*hnf+1] = exp2f(s11 - mn1);
          }
        }
        t0 += (e0[0] + e0[1]) + (e0[2] + e0[3]);
        t1 += (e1[0] + e1[1]) + (e1[2] + e1[3]);
        uint32_t pfrag[4];
        {
          __half2 p0 = __floats2half2_rn(e0[0], e0[1]);
          __half2 p1 = __floats2half2_rn(e1[0], e1[1]);
          __half2 p2 = __floats2half2_rn(e0[2], e0[3]);
          __half2 p3 = __floats2half2_rn(e1[2], e1[3]);
          pfrag[0] = *(uint32_t*)&p0; pfrag[1] = *(uint32_t*)&p1;
          pfrag[2] = *(uint32_t*)&p2; pfrag[3] = *(uint32_t*)&p3;
        }
        #pragma unroll
        for (int dc = 0; dc < 8; dc++){
          uint32_t addr = svb + (kc*16 + jrow)*VPITCH + (dc*16 + dsel)*2;
          uint32_t v0, v1, v2, v3;
          ldmx4t(v0, v1, v2, v3, addr);
          mma16816(of[dc*2    ], pfrag, v0, v1);
          mma16816(of[dc*2 + 1], pfrag, v2, v3);
        }
      }
      l0 = l0*a0 + t0; l1 = l1*a1 + t1;
      m0 = mn0; m1 = mn1;
      __syncthreads();
    }

    // --- epilogue: reduce l over quad, normalize, f16-round, add v_mean ---
    l0 += __shfl_xor_sync(0xffffffffu, l0, 1);
    l0 += __shfl_xor_sync(0xffffffffu, l0, 2);
    l1 += __shfl_xor_sync(0xffffffffu, l1, 1);
    l1 += __shfl_xor_sync(0xffffffffu, l1, 2);
    float inv0 = 1.0f / l0, inv1 = 1.0f / l1;
    float* ob = out + ((size_t)b*SS)*HID + h*DD;
    const float* vm = g_vmean + bh*DD;
    #pragma unroll
    for (int n = 0; n < 16; n++){
      int d0 = n*8 + q2;
      float2 o0, o1;
      o0.x = __half2float(__float2half_rn(of[n][0]*inv0)) + vm[d0];
      o0.y = __half2float(__float2half_rn(of[n][1]*inv0)) + vm[d0+1];
      o1.x = __half2float(__float2half_rn(of[n][2]*inv1)) + vm[d0];
      o1.y = __half2float(__float2half_rn(of[n][3]*inv1)) + vm[d0+1];
      *(float2*)(ob + (size_t)i_r0*HID + d0) = o0;
      *(float2*)(ob + (size_t)i_r1*HID + d0) = o1;
    }

    // --- grab next work item ---
    if (tid == 0) s_next = atomicAdd(&g_wq, 1);
    __syncthreads();
    wi = s_next;
  }
}

// ---------------- launch ----------------
extern "C" void kernel_launch(void* const* d_in, const int* in_sizes, int n_in,
                              void* d_out, int out_size){
  const float* q = (const float*)d_in[0];
  const float* k = (const float*)d_in[1];
  const float* v = (const float*)d_in[2];
  const int* wl  = (const int*)d_in[3];
  const int* wr  = (const int*)d_in[4];
  float* out = (float*)d_out;

  cudaFuncSetAttribute(attn_kernel, cudaFuncAttributeMaxDynamicSharedMemorySize, SMEM_TOTAL);

  pre_k0<<<dim3(16, BB*HH), 256>>>(k, v);
  pre_k2<<<dim3(64, BB*HH), 256>>>(k, v);
  attn_kernel<<<ATTN_GRID, 128, SMEM_TOTAL>>>(q, wl, wr, out);
}